// round 3
// baseline (speedup 1.0000x reference)
#include <cuda_runtime.h>
#include <cuda_bf16.h>
#include <math.h>

// Problem constants
#define BATCH 2
#define SEQ   2048
#define DMODEL 1024
#define NHEAD 16
#define DHEAD 64
#define DFF   4096
#define ROWS  (BATCH*SEQ)   // 4096

// ----------------------------------------------------------------------------
// Scratch (device globals; no allocations allowed)
// ----------------------------------------------------------------------------
__device__ float g_h   [(size_t)ROWS*DMODEL];      // rmsnorm output (reused)
__device__ float g_tmp [(size_t)ROWS*DMODEL];      // linear output before transpose
__device__ float g_q   [(size_t)ROWS*DMODEL];      // [B,H,S,DK]
__device__ float g_k   [(size_t)ROWS*DMODEL];
__device__ float g_v   [(size_t)ROWS*DMODEL];
__device__ float g_ctx [(size_t)ROWS*DMODEL];      // [B,S,D]
__device__ float g_x2  [(size_t)ROWS*DMODEL];      // post-attention residual
__device__ float g_u   [(size_t)ROWS*2*DFF];       // FFN up-proj  (134 MB)
__device__ float g_ffn [(size_t)ROWS*DFF];         // swiglu out   (67 MB)
__device__ float g_cos [SEQ*32];
__device__ float g_sin [SEQ*32];

// ----------------------------------------------------------------------------
// RoPE table (double precision: matches true math to ~1e-16; jax fp32 own error
// dominates the comparison at ~1e-4 in angle which is fine for 1e-3 rel_err)
// ----------------------------------------------------------------------------
__global__ void build_rope_table() {
    int idx = blockIdx.x * blockDim.x + threadIdx.x;
    if (idx >= SEQ * 32) return;
    int s = idx / 32, j = idx % 32;
    double invf = exp(-(double)j * (9.210340371976184 / 32.0)); // 10000^(-j/32)
    double a = (double)s * invf;
    g_cos[idx] = (float)cos(a);
    g_sin[idx] = (float)sin(a);
}

// ----------------------------------------------------------------------------
// RMSNorm: one block per row of 1024
// ----------------------------------------------------------------------------
__global__ __launch_bounds__(256) void rmsnorm_k(const float* __restrict__ x,
                                                 const float* __restrict__ g,
                                                 float* __restrict__ o) {
    int row = blockIdx.x;
    const float* xr = x + (size_t)row * DMODEL;
    float ss = 0.f;
    for (int c = threadIdx.x; c < DMODEL; c += 256) { float v = xr[c]; ss += v * v; }
    __shared__ float sm[8];
    for (int off = 16; off; off >>= 1) ss += __shfl_down_sync(0xffffffffu, ss, off);
    if ((threadIdx.x & 31) == 0) sm[threadIdx.x >> 5] = ss;
    __syncthreads();
    if (threadIdx.x < 8) {
        float v = sm[threadIdx.x];
        for (int off = 4; off; off >>= 1) v += __shfl_down_sync(0xffu, v, off);
        if (threadIdx.x == 0) sm[0] = v;
    }
    __syncthreads();
    float inv = 1.0f / sqrtf(sm[0] / (float)DMODEL + 1e-6f);
    float* orow = o + (size_t)row * DMODEL;
    for (int c = threadIdx.x; c < DMODEL; c += 256) orow[c] = xr[c] * inv * g[c];
}

// ----------------------------------------------------------------------------
// NT SGEMM: C[M,N] = A[M,K] @ B[N,K]^T (+ residual). 128x128x16 tile,
// 256 threads, 8x8 micro-tile. All dims assumed divisible (they are).
// ----------------------------------------------------------------------------
__global__ __launch_bounds__(256) void gemm_nt(const float* __restrict__ A,
                                               const float* __restrict__ B,
                                               const float* __restrict__ res,
                                               float* __restrict__ C,
                                               int M, int N, int K) {
    const int BM = 128, BN = 128, BK = 16;
    __shared__ float As[BK][BM];
    __shared__ float Bs[BK][BN];
    int bx = blockIdx.x, by = blockIdx.y;
    int tid = threadIdx.x;
    int tx = tid & 15, ty = tid >> 4;
    float acc[8][8] = {};
    const float* Atile = A + (size_t)by * BM * K;
    const float* Btile = B + (size_t)bx * BN * K;

    for (int k0 = 0; k0 < K; k0 += BK) {
#pragma unroll
        for (int it = 0; it < 2; it++) {
            int idx = tid + it * 256;           // 0..511 float4 slots
            int row = idx >> 2;                 // 0..127
            int c4  = (idx & 3) * 4;            // 0,4,8,12
            float4 va = *reinterpret_cast<const float4*>(Atile + (size_t)row * K + k0 + c4);
            As[c4 + 0][row] = va.x; As[c4 + 1][row] = va.y;
            As[c4 + 2][row] = va.z; As[c4 + 3][row] = va.w;
            float4 vb = *reinterpret_cast<const float4*>(Btile + (size_t)row * K + k0 + c4);
            Bs[c4 + 0][row] = vb.x; Bs[c4 + 1][row] = vb.y;
            Bs[c4 + 2][row] = vb.z; Bs[c4 + 3][row] = vb.w;
        }
        __syncthreads();
#pragma unroll
        for (int kk = 0; kk < BK; kk++) {
            float a[8], b[8];
            float4 a0 = *reinterpret_cast<const float4*>(&As[kk][ty * 8]);
            float4 a1 = *reinterpret_cast<const float4*>(&As[kk][ty * 8 + 4]);
            a[0]=a0.x; a[1]=a0.y; a[2]=a0.z; a[3]=a0.w;
            a[4]=a1.x; a[5]=a1.y; a[6]=a1.z; a[7]=a1.w;
            float4 b0 = *reinterpret_cast<const float4*>(&Bs[kk][tx * 8]);
            float4 b1 = *reinterpret_cast<const float4*>(&Bs[kk][tx * 8 + 4]);
            b[0]=b0.x; b[1]=b0.y; b[2]=b0.z; b[3]=b0.w;
            b[4]=b1.x; b[5]=b1.y; b[6]=b1.z; b[7]=b1.w;
#pragma unroll
            for (int i = 0; i < 8; i++)
#pragma unroll
                for (int j = 0; j < 8; j++) acc[i][j] += a[i] * b[j];
        }
        __syncthreads();
    }

#pragma unroll
    for (int i = 0; i < 8; i++) {
        int r = by * BM + ty * 8 + i;
#pragma unroll
        for (int j = 0; j < 8; j += 4) {
            int c = bx * BN + tx * 8 + j;
            float4 o;
            o.x = acc[i][j]; o.y = acc[i][j+1]; o.z = acc[i][j+2]; o.w = acc[i][j+3];
            if (res) {
                float4 rv = *reinterpret_cast<const float4*>(res + (size_t)r * N + c);
                o.x += rv.x; o.y += rv.y; o.z += rv.z; o.w += rv.w;
            }
            *reinterpret_cast<float4*>(C + (size_t)r * N + c) = o;
        }
    }
}

// ----------------------------------------------------------------------------
// RoPE + transpose [B,S,D] -> [B,H,S,DK]  (applyRope=0 for V: transpose only)
// ----------------------------------------------------------------------------
__global__ __launch_bounds__(256) void rope_tr(const float* __restrict__ lin,
                                               float* __restrict__ outp,
                                               int applyRope) {
    int row = blockIdx.x;              // 0..4095
    int b = row >> 11, s = row & 2047;
    const float* lr = lin + (size_t)row * DMODEL;
    for (int c = threadIdx.x; c < DMODEL; c += 256) {
        int h = c >> 6, dk = c & 63, j = dk & 31;
        float v = lr[c];
        float o = v;
        if (applyRope) {
            float cs = g_cos[s * 32 + j];
            float sn = g_sin[s * 32 + j];
            float rot = (dk < 32) ? -lr[c + 32] : lr[c - 32];
            o = v * cs + rot * sn;
        }
        outp[(((size_t)(b * NHEAD + h)) * SEQ + s) * DHEAD + dk] = o;
    }
}

// ----------------------------------------------------------------------------
// Flash attention, causal. Block = (q-tile of 64, one (b,h)). Key tiles of 32.
// 256 threads: 16x16. S partition: 4x2 per thread; O partition: 4x4 per thread.
// ----------------------------------------------------------------------------
__global__ __launch_bounds__(256) void flash_attn(const float* __restrict__ Q,
                                                  const float* __restrict__ K,
                                                  const float* __restrict__ V,
                                                  float* __restrict__ ctx) {
    int qt = blockIdx.x;           // 0..31
    int bh = blockIdx.y;           // 0..31
    int tid = threadIdx.x;
    int tx = tid & 15, ty = tid >> 4;

    __shared__ float Qs[64][64];
    __shared__ float KsT[64][33];
    __shared__ float Vs[32][64];
    __shared__ float Ss[64][33];
    __shared__ float rowm[64], rowl[64], rowsc[64];

    const size_t baseQ = ((size_t)bh * SEQ + (size_t)qt * 64) * DHEAD;
#pragma unroll
    for (int it = 0; it < 4; it++) {
        int idx = tid + it * 256;
        int r = idx >> 4, c4 = (idx & 15) * 4;
        *reinterpret_cast<float4*>(&Qs[r][c4]) =
            *reinterpret_cast<const float4*>(Q + baseQ + (size_t)r * 64 + c4);
    }
    if (tid < 64) { rowm[tid] = -1e30f; rowl[tid] = 0.f; }
    float o[4][4] = {};
    __syncthreads();

    int qbase = qt * 64;
    int ntile = 2 * (qt + 1);
    for (int kt = 0; kt < ntile; kt++) {
        int kb = kt * 32;
        const float* Kb = K + ((size_t)bh * SEQ + kb) * DHEAD;
        const float* Vb = V + ((size_t)bh * SEQ + kb) * DHEAD;
#pragma unroll
        for (int it = 0; it < 2; it++) {
            int idx = tid + it * 256;         // 512 float4
            int r = idx >> 4, c4 = (idx & 15) * 4;
            float4 kv = *reinterpret_cast<const float4*>(Kb + (size_t)r * 64 + c4);
            KsT[c4 + 0][r] = kv.x; KsT[c4 + 1][r] = kv.y;
            KsT[c4 + 2][r] = kv.z; KsT[c4 + 3][r] = kv.w;
            *reinterpret_cast<float4*>(&Vs[r][c4]) =
                *reinterpret_cast<const float4*>(Vb + (size_t)r * 64 + c4);
        }
        __syncthreads();

        float sacc[4][2] = {};
#pragma unroll 8
        for (int kk = 0; kk < 64; kk++) {
            float q0 = Qs[ty * 4 + 0][kk], q1 = Qs[ty * 4 + 1][kk];
            float q2 = Qs[ty * 4 + 2][kk], q3 = Qs[ty * 4 + 3][kk];
            float k0 = KsT[kk][tx * 2 + 0], k1 = KsT[kk][tx * 2 + 1];
            sacc[0][0] += q0 * k0; sacc[0][1] += q0 * k1;
            sacc[1][0] += q1 * k0; sacc[1][1] += q1 * k1;
            sacc[2][0] += q2 * k0; sacc[2][1] += q2 * k1;
            sacc[3][0] += q3 * k0; sacc[3][1] += q3 * k1;
        }
#pragma unroll
        for (int i = 0; i < 4; i++)
#pragma unroll
            for (int j = 0; j < 2; j++) {
                int r = ty * 4 + i, c = tx * 2 + j;
                int qg = qbase + r, kg = kb + c;
                Ss[r][c] = (kg <= qg) ? sacc[i][j] * 0.125f : -1e9f;
            }
        __syncthreads();

        if (tid < 64) {
            int r = tid;
            float m = rowm[r], mn = m;
            for (int c = 0; c < 32; c++) mn = fmaxf(mn, Ss[r][c]);
            float sc = expf(m - mn);
            float l = rowl[r] * sc;
            for (int c = 0; c < 32; c++) {
                float e = expf(Ss[r][c] - mn);
                Ss[r][c] = e; l += e;
            }
            rowm[r] = mn; rowl[r] = l; rowsc[r] = sc;
        }
        __syncthreads();

#pragma unroll
        for (int i = 0; i < 4; i++) {
            float sc = rowsc[ty * 4 + i];
#pragma unroll
            for (int j = 0; j < 4; j++) o[i][j] *= sc;
        }
#pragma unroll 8
        for (int kk = 0; kk < 32; kk++) {
            float p0 = Ss[ty * 4 + 0][kk], p1 = Ss[ty * 4 + 1][kk];
            float p2 = Ss[ty * 4 + 2][kk], p3 = Ss[ty * 4 + 3][kk];
            float v0 = Vs[kk][tx * 4 + 0], v1 = Vs[kk][tx * 4 + 1];
            float v2 = Vs[kk][tx * 4 + 2], v3 = Vs[kk][tx * 4 + 3];
            o[0][0] += p0 * v0; o[0][1] += p0 * v1; o[0][2] += p0 * v2; o[0][3] += p0 * v3;
            o[1][0] += p1 * v0; o[1][1] += p1 * v1; o[1][2] += p1 * v2; o[1][3] += p1 * v3;
            o[2][0] += p2 * v0; o[2][1] += p2 * v1; o[2][2] += p2 * v2; o[2][3] += p2 * v3;
            o[3][0] += p3 * v0; o[3][1] += p3 * v1; o[3][2] += p3 * v2; o[3][3] += p3 * v3;
        }
        __syncthreads();
    }

    int b = bh >> 4, h = bh & 15;
#pragma unroll
    for (int i = 0; i < 4; i++) {
        int r = ty * 4 + i;
        size_t grow = (size_t)b * SEQ + qbase + r;
        float invl = 1.0f / rowl[r];
#pragma unroll
        for (int j = 0; j < 4; j++)
            ctx[grow * DMODEL + h * 64 + tx * 4 + j] = o[i][j] * invl;
    }
}

// ----------------------------------------------------------------------------
// SwiGLU: ffn = u1 * silu(u2), u = [4096, 2*DFF]
// ----------------------------------------------------------------------------
__global__ __launch_bounds__(256) void swiglu_k(const float* __restrict__ u,
                                                float* __restrict__ f) {
    size_t i = (size_t)blockIdx.x * blockDim.x + threadIdx.x;
    if (i >= (size_t)ROWS * DFF) return;
    size_t row = i / DFF, col = i % DFF;
    float a = u[row * (2 * DFF) + col];
    float b = u[row * (2 * DFF) + DFF + col];
    f[i] = a * (b / (1.0f + expf(-b)));
}

// ----------------------------------------------------------------------------
// Launch
// ----------------------------------------------------------------------------
extern "C" void kernel_launch(void* const* d_in, const int* in_sizes, int n_in,
                              void* d_out, int out_size) {
    const float* x  = (const float*)d_in[0];
    // d_in[1] = mask (causal tril; handled analytically)
    const float* wq = (const float*)d_in[2];
    const float* wk = (const float*)d_in[3];
    const float* wv = (const float*)d_in[4];
    const float* wo = (const float*)d_in[5];
    const float* w1 = (const float*)d_in[6];
    const float* w2 = (const float*)d_in[7];
    const float* g1 = (const float*)d_in[8];
    const float* g2 = (const float*)d_in[9];
    float* out = (float*)d_out;

    static float *p_h=nullptr,*p_tmp=nullptr,*p_q=nullptr,*p_k=nullptr,*p_v=nullptr,
                 *p_ctx=nullptr,*p_x2=nullptr,*p_u=nullptr,*p_ffn=nullptr;
    if (!p_h) {
        cudaGetSymbolAddress((void**)&p_h,   g_h);
        cudaGetSymbolAddress((void**)&p_tmp, g_tmp);
        cudaGetSymbolAddress((void**)&p_q,   g_q);
        cudaGetSymbolAddress((void**)&p_k,   g_k);
        cudaGetSymbolAddress((void**)&p_v,   g_v);
        cudaGetSymbolAddress((void**)&p_ctx, g_ctx);
        cudaGetSymbolAddress((void**)&p_x2,  g_x2);
        cudaGetSymbolAddress((void**)&p_u,   g_u);
        cudaGetSymbolAddress((void**)&p_ffn, g_ffn);
    }

    build_rope_table<<<(SEQ * 32 + 255) / 256, 256>>>();

    // --- attention sublayer ---
    rmsnorm_k<<<ROWS, 256>>>(x, g1, p_h);

    dim3 gproj(DMODEL / 128, ROWS / 128);   // (8, 32)
    gemm_nt<<<gproj, 256>>>(p_h, wq, nullptr, p_tmp, ROWS, DMODEL, DMODEL);
    rope_tr<<<ROWS, 256>>>(p_tmp, p_q, 1);
    gemm_nt<<<gproj, 256>>>(p_h, wk, nullptr, p_tmp, ROWS, DMODEL, DMODEL);
    rope_tr<<<ROWS, 256>>>(p_tmp, p_k, 1);
    gemm_nt<<<gproj, 256>>>(p_h, wv, nullptr, p_tmp, ROWS, DMODEL, DMODEL);
    rope_tr<<<ROWS, 256>>>(p_tmp, p_v, 0);

    flash_attn<<<dim3(SEQ / 64, BATCH * NHEAD), 256>>>(p_q, p_k, p_v, p_ctx);

    gemm_nt<<<gproj, 256>>>(p_ctx, wo, x, p_x2, ROWS, DMODEL, DMODEL);

    // --- FFN sublayer ---
    rmsnorm_k<<<ROWS, 256>>>(p_x2, g2, p_h);
    dim3 gup(2 * DFF / 128, ROWS / 128);    // (64, 32)
    gemm_nt<<<gup, 256>>>(p_h, w1, nullptr, p_u, ROWS, 2 * DFF, DMODEL);
    swiglu_k<<<(unsigned)(((size_t)ROWS * DFF + 255) / 256), 256>>>(p_u, p_ffn);
    dim3 gdown(DMODEL / 128, ROWS / 128);   // (8, 32)
    gemm_nt<<<gdown, 256>>>(p_ffn, w2, p_x2, out, ROWS, DMODEL, DFF);
}

// round 5
// speedup vs baseline: 1.9422x; 1.9422x over previous
#include <cuda_runtime.h>
#include <cuda_bf16.h>
#include <math.h>
#include <stdint.h>

// Problem constants
#define BATCH 2
#define SEQ   2048
#define DMODEL 1024
#define NHEAD 16
#define DHEAD 64
#define DFF   4096
#define ROWS  (BATCH*SEQ)   // 4096

// ----------------------------------------------------------------------------
// Scratch (device globals; no allocations allowed)
// ----------------------------------------------------------------------------
__device__ float g_h   [(size_t)ROWS*DMODEL];
__device__ float g_tmp [(size_t)ROWS*DMODEL];
__device__ float g_q   [(size_t)ROWS*DMODEL];
__device__ float g_k   [(size_t)ROWS*DMODEL];
__device__ float g_v   [(size_t)ROWS*DMODEL];
__device__ float g_ctx [(size_t)ROWS*DMODEL];
__device__ float g_x2  [(size_t)ROWS*DMODEL];
__device__ float g_u   [(size_t)ROWS*2*DFF];
__device__ float g_ffn [(size_t)ROWS*DFF];
__device__ float g_cos [SEQ*32];
__device__ float g_sin [SEQ*32];
// tf32-rounded weights
__device__ float g_wq_r[(size_t)DMODEL*DMODEL];
__device__ float g_wk_r[(size_t)DMODEL*DMODEL];
__device__ float g_wv_r[(size_t)DMODEL*DMODEL];
__device__ float g_wo_r[(size_t)DMODEL*DMODEL];
__device__ float g_w1_r[(size_t)2*DFF*DMODEL];
__device__ float g_w2_r[(size_t)DMODEL*DFF];

// ----------------------------------------------------------------------------
// Helpers
// ----------------------------------------------------------------------------
__device__ __forceinline__ float tf32r(float x) {
    uint32_t u;
    asm("cvt.rna.tf32.f32 %0, %1;" : "=r"(u) : "f"(x));
    return __uint_as_float(u);
}
__device__ __forceinline__ uint32_t smem_u32(const void* p) {
    uint32_t a;
    asm("{ .reg .u64 t; cvta.to.shared.u64 t, %1; cvt.u32.u64 %0, t; }" : "=r"(a) : "l"(p));
    return a;
}
__device__ __forceinline__ void cp16(uint32_t dst, const void* src) {
    asm volatile("cp.async.ca.shared.global [%0], [%1], 16;" :: "r"(dst), "l"(src) : "memory");
}
#define CP_COMMIT() asm volatile("cp.async.commit_group;" ::: "memory")
#define CP_WAIT1()  asm volatile("cp.async.wait_group 1;" ::: "memory")

__device__ __forceinline__ void mma_tf32(float* c, const uint32_t* a, const uint32_t* b) {
    asm volatile("mma.sync.aligned.m16n8k8.row.col.f32.tf32.tf32.f32 "
                 "{%0,%1,%2,%3}, {%4,%5,%6,%7}, {%8,%9}, {%0,%1,%2,%3};"
                 : "+f"(c[0]), "+f"(c[1]), "+f"(c[2]), "+f"(c[3])
                 : "r"(a[0]), "r"(a[1]), "r"(a[2]), "r"(a[3]), "r"(b[0]), "r"(b[1]));
}

// ----------------------------------------------------------------------------
// RoPE table
// ----------------------------------------------------------------------------
__global__ void build_rope_table() {
    int idx = blockIdx.x * blockDim.x + threadIdx.x;
    if (idx >= SEQ * 32) return;
    int s = idx / 32, j = idx % 32;
    double invf = exp(-(double)j * (9.210340371976184 / 32.0));
    double a = (double)s * invf;
    g_cos[idx] = (float)cos(a);
    g_sin[idx] = (float)sin(a);
}

// ----------------------------------------------------------------------------
// tf32 rounding of weights
// ----------------------------------------------------------------------------
__global__ __launch_bounds__(256) void round_tf32_k(const float4* __restrict__ in,
                                                    float4* __restrict__ out, int n4) {
    int i = blockIdx.x * 256 + threadIdx.x;
    if (i >= n4) return;
    float4 v = in[i];
    v.x = tf32r(v.x); v.y = tf32r(v.y); v.z = tf32r(v.z); v.w = tf32r(v.w);
    out[i] = v;
}

// ----------------------------------------------------------------------------
// RMSNorm (tf32-rounded output: feeds tensor-core GEMMs)
// ----------------------------------------------------------------------------
__global__ __launch_bounds__(256) void rmsnorm_k(const float* __restrict__ x,
                                                 const float* __restrict__ g,
                                                 float* __restrict__ o) {
    int row = blockIdx.x;
    const float* xr = x + (size_t)row * DMODEL;
    float ss = 0.f;
    for (int c = threadIdx.x; c < DMODEL; c += 256) { float v = xr[c]; ss += v * v; }
    __shared__ float sm[8];
    for (int off = 16; off; off >>= 1) ss += __shfl_down_sync(0xffffffffu, ss, off);
    if ((threadIdx.x & 31) == 0) sm[threadIdx.x >> 5] = ss;
    __syncthreads();
    if (threadIdx.x < 8) {
        float v = sm[threadIdx.x];
        for (int off = 4; off; off >>= 1) v += __shfl_down_sync(0xffu, v, off);
        if (threadIdx.x == 0) sm[0] = v;
    }
    __syncthreads();
    float inv = 1.0f / sqrtf(sm[0] / (float)DMODEL + 1e-6f);
    float* orow = o + (size_t)row * DMODEL;
    for (int c = threadIdx.x; c < DMODEL; c += 256) orow[c] = tf32r(xr[c] * inv * g[c]);
}

// ----------------------------------------------------------------------------
// TF32 mma.sync GEMM: C[M,N] = A[M,K] @ B[N,K]^T (+res).
// BM=128 BN=128 BK=16, 256 threads, 8 warps (4 m x 2 n), warp tile 32x64.
// 3-stage cp.async pipeline. Inputs must already be tf32-rounded.
// ----------------------------------------------------------------------------
#define BK 16
#define LDT 20                      // padded row stride in floats
#define STG_F (128*LDT)             // floats per matrix per stage
#define GSTAGES 3
#define GEMM_SMEM (GSTAGES*2*STG_F*4)   // 61440 bytes

__global__ void __launch_bounds__(256, 1) gemm_mma(
    const float* __restrict__ A, const float* __restrict__ B,
    const float* __restrict__ res, float* __restrict__ C,
    int M, int N, int K)
{
    extern __shared__ float smf[];
    float* As = smf;
    float* Bs = smf + GSTAGES * STG_F;
    const uint32_t asu = smem_u32(As);
    const uint32_t bsu = smem_u32(Bs);

    const int tid = threadIdx.x;
    const int wid = tid >> 5, lane = tid & 31;
    const int wm = wid & 3, wn = wid >> 2;       // warp grid 4x2
    const int g = lane >> 2, tg = lane & 3;
    const int m0 = blockIdx.y * 128, n0 = blockIdx.x * 128;

    const int ldr0 = tid >> 2;                   // load row for idx=tid
    const int ldc0 = (tid & 3) * 4;              // load col
    const float* Ag = A + (size_t)(m0 + ldr0) * K + ldc0;
    const float* Bg = B + (size_t)(n0 + ldr0) * K + ldc0;
    const float* Ag2 = Ag + (size_t)64 * K;      // second half (rows +64)
    const float* Bg2 = Bg + (size_t)64 * K;

    const int niter = K >> 4;

    // prologue: stages 0..GSTAGES-2
#pragma unroll
    for (int s = 0; s < GSTAGES - 1; s++) {
        uint32_t da = asu + (s * STG_F + ldr0 * LDT + ldc0) * 4;
        uint32_t db = bsu + (s * STG_F + ldr0 * LDT + ldc0) * 4;
        cp16(da,                Ag  + s * BK);
        cp16(da + 64 * LDT * 4, Ag2 + s * BK);
        cp16(db,                Bg  + s * BK);
        cp16(db + 64 * LDT * 4, Bg2 + s * BK);
        CP_COMMIT();
    }

    float c[2][8][4] = {};

    for (int i = 0; i < niter; i++) {
        CP_WAIT1();
        __syncthreads();

        int nb = i + GSTAGES - 1;
        if (nb < niter) {
            int s = nb % GSTAGES;
            uint32_t da = asu + (s * STG_F + ldr0 * LDT + ldc0) * 4;
            uint32_t db = bsu + (s * STG_F + ldr0 * LDT + ldc0) * 4;
            cp16(da,                Ag  + nb * BK);
            cp16(da + 64 * LDT * 4, Ag2 + nb * BK);
            cp16(db,                Bg  + nb * BK);
            cp16(db + 64 * LDT * 4, Bg2 + nb * BK);
        }
        CP_COMMIT();

        const float* as = As + (i % GSTAGES) * STG_F + (wm * 32) * LDT;
        const float* bs = Bs + (i % GSTAGES) * STG_F + (wn * 64) * LDT;
#pragma unroll
        for (int ks = 0; ks < 2; ks++) {
            int k0 = ks * 8;
            uint32_t a[2][4], b[8][2];
#pragma unroll
            for (int mi = 0; mi < 2; mi++) {
                const float* ap = as + (mi * 16 + g) * LDT + k0 + tg;
                a[mi][0] = __float_as_uint(ap[0]);
                a[mi][1] = __float_as_uint(ap[8 * LDT]);
                a[mi][2] = __float_as_uint(ap[4]);
                a[mi][3] = __float_as_uint(ap[8 * LDT + 4]);
            }
#pragma unroll
            for (int ni = 0; ni < 8; ni++) {
                const float* bp = bs + (ni * 8 + g) * LDT + k0 + tg;
                b[ni][0] = __float_as_uint(bp[0]);
                b[ni][1] = __float_as_uint(bp[4]);
            }
#pragma unroll
            for (int mi = 0; mi < 2; mi++)
#pragma unroll
                for (int ni = 0; ni < 8; ni++)
                    mma_tf32(c[mi][ni], a[mi], b[ni]);
        }
        __syncthreads();
    }

    // epilogue: write C (+residual)
#pragma unroll
    for (int mi = 0; mi < 2; mi++) {
        int r0 = m0 + wm * 32 + mi * 16 + g;
#pragma unroll
        for (int ni = 0; ni < 8; ni++) {
            int cc = n0 + wn * 64 + ni * 8 + tg * 2;
            size_t o1 = (size_t)r0 * N + cc;
            size_t o2 = (size_t)(r0 + 8) * N + cc;
            float2 v1 = make_float2(c[mi][ni][0], c[mi][ni][1]);
            float2 v2 = make_float2(c[mi][ni][2], c[mi][ni][3]);
            if (res) {
                float2 r1 = *reinterpret_cast<const float2*>(res + o1);
                float2 r2 = *reinterpret_cast<const float2*>(res + o2);
                v1.x += r1.x; v1.y += r1.y; v2.x += r2.x; v2.y += r2.y;
            }
            *reinterpret_cast<float2*>(C + o1) = v1;
            *reinterpret_cast<float2*>(C + o2) = v2;
        }
    }
}

// ----------------------------------------------------------------------------
// RoPE + transpose [B,S,D] -> [B,H,S,DK]
// ----------------------------------------------------------------------------
__global__ __launch_bounds__(256) void rope_tr(const float* __restrict__ lin,
                                               float* __restrict__ outp,
                                               int applyRope) {
    int row = blockIdx.x;
    int b = row >> 11, s = row & 2047;
    const float* lr = lin + (size_t)row * DMODEL;
    for (int c = threadIdx.x; c < DMODEL; c += 256) {
        int h = c >> 6, dk = c & 63, j = dk & 31;
        float v = lr[c];
        float o = v;
        if (applyRope) {
            float cs = g_cos[s * 32 + j];
            float sn = g_sin[s * 32 + j];
            float rot = (dk < 32) ? -lr[c + 32] : lr[c - 32];
            o = v * cs + rot * sn;
        }
        outp[(((size_t)(b * NHEAD + h)) * SEQ + s) * DHEAD + dk] = o;
    }
}

// ----------------------------------------------------------------------------
// Flash attention, causal; parallel online softmax; tf32-rounded output.
// ----------------------------------------------------------------------------
__global__ __launch_bounds__(256) void flash_attn(const float* __restrict__ Q,
                                                  const float* __restrict__ K,
                                                  const float* __restrict__ V,
                                                  float* __restrict__ ctx) {
    int qt = blockIdx.x;
    int bh = blockIdx.y;
    int tid = threadIdx.x;
    int tx = tid & 15, ty = tid >> 4;

    __shared__ float Qs[64][64];
    __shared__ float KsT[64][33];
    __shared__ float Vs[32][64];
    __shared__ float Ss[64][33];
    __shared__ float rowm[64], rowl[64], rowsc[64];

    const size_t baseQ = ((size_t)bh * SEQ + (size_t)qt * 64) * DHEAD;
#pragma unroll
    for (int it = 0; it < 4; it++) {
        int idx = tid + it * 256;
        int r = idx >> 4, c4 = (idx & 15) * 4;
        *reinterpret_cast<float4*>(&Qs[r][c4]) =
            *reinterpret_cast<const float4*>(Q + baseQ + (size_t)r * 64 + c4);
    }
    if (tid < 64) { rowm[tid] = -1e30f; rowl[tid] = 0.f; }
    float o[4][4] = {};
    __syncthreads();

    int qbase = qt * 64;
    int ntile = 2 * (qt + 1);
    for (int kt = 0; kt < ntile; kt++) {
        int kb = kt * 32;
        const float* Kb = K + ((size_t)bh * SEQ + kb) * DHEAD;
        const float* Vb = V + ((size_t)bh * SEQ + kb) * DHEAD;
#pragma unroll
        for (int it = 0; it < 2; it++) {
            int idx = tid + it * 256;
            int r = idx >> 4, c4 = (idx & 15) * 4;
            float4 kv = *reinterpret_cast<const float4*>(Kb + (size_t)r * 64 + c4);
            KsT[c4 + 0][r] = kv.x; KsT[c4 + 1][r] = kv.y;
            KsT[c4 + 2][r] = kv.z; KsT[c4 + 3][r] = kv.w;
            *reinterpret_cast<float4*>(&Vs[r][c4]) =
                *reinterpret_cast<const float4*>(Vb + (size_t)r * 64 + c4);
        }
        __syncthreads();

        float sacc[4][2] = {};
#pragma unroll 8
        for (int kk = 0; kk < 64; kk++) {
            float q0 = Qs[ty * 4 + 0][kk], q1 = Qs[ty * 4 + 1][kk];
            float q2 = Qs[ty * 4 + 2][kk], q3 = Qs[ty * 4 + 3][kk];
            float k0 = KsT[kk][tx * 2 + 0], k1 = KsT[kk][tx * 2 + 1];
            sacc[0][0] += q0 * k0; sacc[0][1] += q0 * k1;
            sacc[1][0] += q1 * k0; sacc[1][1] += q1 * k1;
            sacc[2][0] += q2 * k0; sacc[2][1] += q2 * k1;
            sacc[3][0] += q3 * k0; sacc[3][1] += q3 * k1;
        }
#pragma unroll
        for (int i = 0; i < 4; i++)
#pragma unroll
            for (int j = 0; j < 2; j++) {
                int r = ty * 4 + i, c = tx * 2 + j;
                int qg = qbase + r, kg = kb + c;
                Ss[r][c] = (kg <= qg) ? sacc[i][j] * 0.125f : -1e9f;
            }
        __syncthreads();

        // parallel online softmax: 4 threads per row
        {
            int r = tid >> 2, q = tid & 3;
            float* Sr = &Ss[r][q * 8];
            float mx = fmaxf(fmaxf(fmaxf(Sr[0], Sr[1]), fmaxf(Sr[2], Sr[3])),
                             fmaxf(fmaxf(Sr[4], Sr[5]), fmaxf(Sr[6], Sr[7])));
            mx = fmaxf(mx, __shfl_xor_sync(0xffffffffu, mx, 1));
            mx = fmaxf(mx, __shfl_xor_sync(0xffffffffu, mx, 2));
            float mOld = rowm[r];
            float mn = fmaxf(mOld, mx);
            float l = 0.f;
#pragma unroll
            for (int c = 0; c < 8; c++) {
                float e = __expf(Sr[c] - mn);
                Sr[c] = e; l += e;
            }
            l += __shfl_xor_sync(0xffffffffu, l, 1);
            l += __shfl_xor_sync(0xffffffffu, l, 2);
            if (q == 0) {
                float sc = __expf(mOld - mn);
                rowsc[r] = sc;
                rowl[r] = rowl[r] * sc + l;
                rowm[r] = mn;
            }
        }
        __syncthreads();

#pragma unroll
        for (int i = 0; i < 4; i++) {
            float sc = rowsc[ty * 4 + i];
#pragma unroll
            for (int j = 0; j < 4; j++) o[i][j] *= sc;
        }
#pragma unroll 8
        for (int kk = 0; kk < 32; kk++) {
            float p0 = Ss[ty * 4 + 0][kk], p1 = Ss[ty * 4 + 1][kk];
            float p2 = Ss[ty * 4 + 2][kk], p3 = Ss[ty * 4 + 3][kk];
            float v0 = Vs[kk][tx * 4 + 0], v1 = Vs[kk][tx * 4 + 1];
            float v2 = Vs[kk][tx * 4 + 2], v3 = Vs[kk][tx * 4 + 3];
            o[0][0] += p0 * v0; o[0][1] += p0 * v1; o[0][2] += p0 * v2; o[0][3] += p0 * v3;
            o[1][0] += p1 * v0; o[1][1] += p1 * v1; o[1][2] += p1 * v2; o[1][3] += p1 * v3;
            o[2][0] += p2 * v0; o[2][1] += p2 * v1; o[2][2] += p2 * v2; o[2][3] += p2 * v3;
            o[3][0] += p3 * v0; o[3][1] += p3 * v1; o[3][2] += p3 * v2; o[3][3] += p3 * v3;
        }
        __syncthreads();
    }

    int b = bh >> 4, h = bh & 15;
#pragma unroll
    for (int i = 0; i < 4; i++) {
        int r = ty * 4 + i;
        size_t grow = (size_t)b * SEQ + qbase + r;
        float invl = 1.0f / rowl[r];
#pragma unroll
        for (int j = 0; j < 4; j++)
            ctx[grow * DMODEL + h * 64 + tx * 4 + j] = tf32r(o[i][j] * invl);
    }
}

// ----------------------------------------------------------------------------
// SwiGLU (tf32-rounded output: feeds w2 tensor GEMM)
// ----------------------------------------------------------------------------
__global__ __launch_bounds__(256) void swiglu_k(const float* __restrict__ u,
                                                float* __restrict__ f) {
    size_t i = (size_t)blockIdx.x * blockDim.x + threadIdx.x;
    if (i >= (size_t)ROWS * DFF) return;
    size_t row = i / DFF, col = i % DFF;
    float a = u[row * (2 * DFF) + col];
    float b = u[row * (2 * DFF) + DFF + col];
    f[i] = tf32r(a * (b / (1.0f + expf(-b))));
}

// ----------------------------------------------------------------------------
// Launch
// ----------------------------------------------------------------------------
extern "C" void kernel_launch(void* const* d_in, const int* in_sizes, int n_in,
                              void* d_out, int out_size) {
    const float* x  = (const float*)d_in[0];
    const float* wq = (const float*)d_in[2];
    const float* wk = (const float*)d_in[3];
    const float* wv = (const float*)d_in[4];
    const float* wo = (const float*)d_in[5];
    const float* w1 = (const float*)d_in[6];
    const float* w2 = (const float*)d_in[7];
    const float* g1 = (const float*)d_in[8];
    const float* g2 = (const float*)d_in[9];
    float* out = (float*)d_out;

    static float *p_h=nullptr,*p_tmp=nullptr,*p_q=nullptr,*p_k=nullptr,*p_v=nullptr,
                 *p_ctx=nullptr,*p_x2=nullptr,*p_u=nullptr,*p_ffn=nullptr,
                 *p_wq=nullptr,*p_wk=nullptr,*p_wv=nullptr,*p_wo=nullptr,
                 *p_w1=nullptr,*p_w2=nullptr;
    if (!p_h) {
        cudaGetSymbolAddress((void**)&p_h,   g_h);
        cudaGetSymbolAddress((void**)&p_tmp, g_tmp);
        cudaGetSymbolAddress((void**)&p_q,   g_q);
        cudaGetSymbolAddress((void**)&p_k,   g_k);
        cudaGetSymbolAddress((void**)&p_v,   g_v);
        cudaGetSymbolAddress((void**)&p_ctx, g_ctx);
        cudaGetSymbolAddress((void**)&p_x2,  g_x2);
        cudaGetSymbolAddress((void**)&p_u,   g_u);
        cudaGetSymbolAddress((void**)&p_ffn, g_ffn);
        cudaGetSymbolAddress((void**)&p_wq,  g_wq_r);
        cudaGetSymbolAddress((void**)&p_wk,  g_wk_r);
        cudaGetSymbolAddress((void**)&p_wv,  g_wv_r);
        cudaGetSymbolAddress((void**)&p_wo,  g_wo_r);
        cudaGetSymbolAddress((void**)&p_w1,  g_w1_r);
        cudaGetSymbolAddress((void**)&p_w2,  g_w2_r);
        cudaFuncSetAttribute(gemm_mma, cudaFuncAttributeMaxDynamicSharedMemorySize, GEMM_SMEM);
    }

    build_rope_table<<<(SEQ * 32 + 255) / 256, 256>>>();

    // tf32-round weights into scratch
    round_tf32_k<<<(DMODEL*DMODEL/4 + 255)/256, 256>>>((const float4*)wq, (float4*)p_wq, DMODEL*DMODEL/4);
    round_tf32_k<<<(DMODEL*DMODEL/4 + 255)/256, 256>>>((const float4*)wk, (float4*)p_wk, DMODEL*DMODEL/4);
    round_tf32_k<<<(DMODEL*DMODEL/4 + 255)/256, 256>>>((const float4*)wv, (float4*)p_wv, DMODEL*DMODEL/4);
    round_tf32_k<<<(DMODEL*DMODEL/4 + 255)/256, 256>>>((const float4*)wo, (float4*)p_wo, DMODEL*DMODEL/4);
    round_tf32_k<<<(2*DFF*DMODEL/4 + 255)/256, 256>>>((const float4*)w1, (float4*)p_w1, 2*DFF*DMODEL/4);
    round_tf32_k<<<(DMODEL*DFF/4 + 255)/256, 256>>>((const float4*)w2, (float4*)p_w2, DMODEL*DFF/4);

    // --- attention sublayer ---
    rmsnorm_k<<<ROWS, 256>>>(x, g1, p_h);

    dim3 gproj(DMODEL / 128, ROWS / 128);   // (8, 32)
    gemm_mma<<<gproj, 256, GEMM_SMEM>>>(p_h, p_wq, nullptr, p_tmp, ROWS, DMODEL, DMODEL);
    rope_tr<<<ROWS, 256>>>(p_tmp, p_q, 1);
    gemm_mma<<<gproj, 256, GEMM_SMEM>>>(p_h, p_wk, nullptr, p_tmp, ROWS, DMODEL, DMODEL);
    rope_tr<<<ROWS, 256>>>(p_tmp, p_k, 1);
    gemm_mma<<<gproj, 256, GEMM_SMEM>>>(p_h, p_wv, nullptr, p_tmp, ROWS, DMODEL, DMODEL);
    rope_tr<<<ROWS, 256>>>(p_tmp, p_v, 0);

    flash_attn<<<dim3(SEQ / 64, BATCH * NHEAD), 256>>>(p_q, p_k, p_v, p_ctx);

    gemm_mma<<<gproj, 256, GEMM_SMEM>>>(p_ctx, p_wo, x, p_x2, ROWS, DMODEL, DMODEL);

    // --- FFN sublayer ---
    rmsnorm_k<<<ROWS, 256>>>(p_x2, g2, p_h);
    dim3 gup(2 * DFF / 128, ROWS / 128);    // (64, 32)
    gemm_mma<<<gup, 256, GEMM_SMEM>>>(p_h, p_w1, nullptr, p_u, ROWS, 2 * DFF, DMODEL);
    swiglu_k<<<(unsigned)(((size_t)ROWS * DFF + 255) / 256), 256>>>(p_u, p_ffn);
    dim3 gdown(DMODEL / 128, ROWS / 128);   // (8, 32)
    gemm_mma<<<gdown, 256, GEMM_SMEM>>>(p_ffn, p_w2, p_x2, out, ROWS, DMODEL, DFF);
}

// round 6
// speedup vs baseline: 2.4704x; 1.2720x over previous
#include <cuda_runtime.h>
#include <cuda_bf16.h>
#include <math.h>
#include <stdint.h>

// Problem constants
#define BATCH 2
#define SEQ   2048
#define DMODEL 1024
#define NHEAD 16
#define DHEAD 64
#define DFF   4096
#define ROWS  (BATCH*SEQ)   // 4096

// ----------------------------------------------------------------------------
// Scratch (device globals; no allocations allowed)
// ----------------------------------------------------------------------------
__device__ float g_h   [(size_t)ROWS*DMODEL];
__device__ float g_q   [(size_t)ROWS*DMODEL];
__device__ float g_k   [(size_t)ROWS*DMODEL];
__device__ float g_v   [(size_t)ROWS*DMODEL];
__device__ float g_ctx [(size_t)ROWS*DMODEL];
__device__ float g_x2  [(size_t)ROWS*DMODEL];
__device__ float g_ffn [(size_t)ROWS*DFF];
__device__ float g_cos [SEQ*32];
__device__ float g_sin [SEQ*32];
// tf32-rounded weights
__device__ float g_wq_r[(size_t)DMODEL*DMODEL];
__device__ float g_wk_r[(size_t)DMODEL*DMODEL];
__device__ float g_wv_r[(size_t)DMODEL*DMODEL];
__device__ float g_wo_r[(size_t)DMODEL*DMODEL];
__device__ float g_w1_r[(size_t)2*DFF*DMODEL];   // row-permuted: u1/u2 interleaved
__device__ float g_w2_r[(size_t)DMODEL*DFF];

// ----------------------------------------------------------------------------
// Helpers
// ----------------------------------------------------------------------------
__device__ __forceinline__ float tf32r(float x) {
    uint32_t u;
    asm("cvt.rna.tf32.f32 %0, %1;" : "=r"(u) : "f"(x));
    return __uint_as_float(u);
}
__device__ __forceinline__ uint32_t smem_u32(const void* p) {
    uint32_t a;
    asm("{ .reg .u64 t; cvta.to.shared.u64 t, %1; cvt.u32.u64 %0, t; }" : "=r"(a) : "l"(p));
    return a;
}
__device__ __forceinline__ void cp16(uint32_t dst, const void* src) {
    asm volatile("cp.async.ca.shared.global [%0], [%1], 16;" :: "r"(dst), "l"(src) : "memory");
}
#define CP_COMMIT() asm volatile("cp.async.commit_group;" ::: "memory")
#define CP_WAIT1()  asm volatile("cp.async.wait_group 1;" ::: "memory")

__device__ __forceinline__ void mma_tf32(float* c, const uint32_t* a, uint32_t b0, uint32_t b1) {
    asm volatile("mma.sync.aligned.m16n8k8.row.col.f32.tf32.tf32.f32 "
                 "{%0,%1,%2,%3}, {%4,%5,%6,%7}, {%8,%9}, {%0,%1,%2,%3};"
                 : "+f"(c[0]), "+f"(c[1]), "+f"(c[2]), "+f"(c[3])
                 : "r"(a[0]), "r"(a[1]), "r"(a[2]), "r"(a[3]), "r"(b0), "r"(b1));
}
__device__ __forceinline__ void ldsm4(uint32_t* r, uint32_t addr) {
    asm volatile("ldmatrix.sync.aligned.m8n8.x4.shared.b16 {%0,%1,%2,%3}, [%4];"
                 : "=r"(r[0]), "=r"(r[1]), "=r"(r[2]), "=r"(r[3]) : "r"(addr));
}

// ----------------------------------------------------------------------------
// RoPE table
// ----------------------------------------------------------------------------
__global__ void build_rope_table() {
    int idx = blockIdx.x * blockDim.x + threadIdx.x;
    if (idx >= SEQ * 32) return;
    int s = idx / 32, j = idx % 32;
    double invf = exp(-(double)j * (9.210340371976184 / 32.0));
    double a = (double)s * invf;
    g_cos[idx] = (float)cos(a);
    g_sin[idx] = (float)sin(a);
}

// ----------------------------------------------------------------------------
// tf32 rounding of weights (plain)
// ----------------------------------------------------------------------------
__global__ __launch_bounds__(256) void round_tf32_k(const float4* __restrict__ in,
                                                    float4* __restrict__ out, int n4) {
    int i = blockIdx.x * 256 + threadIdx.x;
    if (i >= n4) return;
    float4 v = in[i];
    v.x = tf32r(v.x); v.y = tf32r(v.y); v.z = tf32r(v.z); v.w = tf32r(v.w);
    out[i] = v;
}

// w1 round + row-permute: dst row 2j <- src j (u1), dst row 2j+1 <- src DFF+j (u2)
__global__ __launch_bounds__(256) void round_perm_w1(const float4* __restrict__ in,
                                                     float4* __restrict__ out) {
    int i = blockIdx.x * 256 + threadIdx.x;
    const int C4 = DMODEL / 4;
    if (i >= 2 * DFF * C4) return;
    int row = i / C4, c = i % C4;
    int src = (row & 1) ? (DFF + (row >> 1)) : (row >> 1);
    float4 v = in[(size_t)src * C4 + c];
    v.x = tf32r(v.x); v.y = tf32r(v.y); v.z = tf32r(v.z); v.w = tf32r(v.w);
    out[i] = v;
}

// ----------------------------------------------------------------------------
// RMSNorm (tf32-rounded output: feeds tensor-core GEMMs)
// ----------------------------------------------------------------------------
__global__ __launch_bounds__(256) void rmsnorm_k(const float* __restrict__ x,
                                                 const float* __restrict__ g,
                                                 float* __restrict__ o) {
    int row = blockIdx.x;
    const float* xr = x + (size_t)row * DMODEL;
    float ss = 0.f;
    for (int c = threadIdx.x; c < DMODEL; c += 256) { float v = xr[c]; ss += v * v; }
    __shared__ float sm[8];
    for (int off = 16; off; off >>= 1) ss += __shfl_down_sync(0xffffffffu, ss, off);
    if ((threadIdx.x & 31) == 0) sm[threadIdx.x >> 5] = ss;
    __syncthreads();
    if (threadIdx.x < 8) {
        float v = sm[threadIdx.x];
        for (int off = 4; off; off >>= 1) v += __shfl_down_sync(0xffu, v, off);
        if (threadIdx.x == 0) sm[0] = v;
    }
    __syncthreads();
    float inv = 1.0f / sqrtf(sm[0] / (float)DMODEL + 1e-6f);
    float* orow = o + (size_t)row * DMODEL;
    for (int c = threadIdx.x; c < DMODEL; c += 256) orow[c] = tf32r(xr[c] * inv * g[c]);
}

// ----------------------------------------------------------------------------
// TF32 mma.sync GEMM with ldmatrix fragments and fused epilogues.
// C[M,N] = A[M,K] @ B[N,K]^T.  BM=128 BN=128 BK=16, 256 thr, warps 4m x 2n.
// MODE 0: plain store (+res).  MODE 1: RoPE + head-transpose.
// MODE 2: head-transpose only. MODE 3: SwiGLU pairs (w1 row-permuted).
// ----------------------------------------------------------------------------
#define BK 16
#define LDT 20
#define STG_F (128*LDT)
#define GSTAGES 3
#define GEMM_SMEM (GSTAGES*2*STG_F*4)   // 61440 bytes

template<int MODE>
__global__ void __launch_bounds__(256, 2) gemm_mma(
    const float* __restrict__ A, const float* __restrict__ B,
    const float* __restrict__ res, float* __restrict__ C,
    int M, int N, int K)
{
    extern __shared__ float smf[];
    float* As = smf;
    float* Bs = smf + GSTAGES * STG_F;
    const uint32_t asu = smem_u32(As);
    const uint32_t bsu = smem_u32(Bs);

    const int tid = threadIdx.x;
    const int wid = tid >> 5, lane = tid & 31;
    const int wm = wid & 3, wn = wid >> 2;       // warp grid 4x2
    const int g = lane >> 2, tg = lane & 3;
    const int m0 = blockIdx.y * 128, n0 = blockIdx.x * 128;

    const int ldr0 = tid >> 2;
    const int ldc0 = (tid & 3) * 4;
    const float* Ag = A + (size_t)(m0 + ldr0) * K + ldc0;
    const float* Bg = B + (size_t)(n0 + ldr0) * K + ldc0;
    const float* Ag2 = Ag + (size_t)64 * K;
    const float* Bg2 = Bg + (size_t)64 * K;

    const int niter = K >> 4;

#pragma unroll
    for (int s = 0; s < GSTAGES - 1; s++) {
        uint32_t da = asu + (s * STG_F + ldr0 * LDT + ldc0) * 4;
        uint32_t db = bsu + (s * STG_F + ldr0 * LDT + ldc0) * 4;
        cp16(da,                Ag  + s * BK);
        cp16(da + 64 * LDT * 4, Ag2 + s * BK);
        cp16(db,                Bg  + s * BK);
        cp16(db + 64 * LDT * 4, Bg2 + s * BK);
        CP_COMMIT();
    }

    float c[2][8][4] = {};

    // ldmatrix per-lane address components
    const int r15 = lane & 15;
    const int ch16 = (lane >> 4) << 4;     // 0 or 16 bytes (tf32 cols 0-3 vs 4-7)
    const uint32_t aAddr0 = (uint32_t)((wm * 32 + r15) * LDT * 4 + ch16);
    const uint32_t bAddr0 = (uint32_t)((wn * 64 + r15) * LDT * 4 + ch16);

    for (int i = 0; i < niter; i++) {
        CP_WAIT1();
        __syncthreads();

        int nb = i + GSTAGES - 1;
        if (nb < niter) {
            int s = nb % GSTAGES;
            uint32_t da = asu + (s * STG_F + ldr0 * LDT + ldc0) * 4;
            uint32_t db = bsu + (s * STG_F + ldr0 * LDT + ldc0) * 4;
            cp16(da,                Ag  + nb * BK);
            cp16(da + 64 * LDT * 4, Ag2 + nb * BK);
            cp16(db,                Bg  + nb * BK);
            cp16(db + 64 * LDT * 4, Bg2 + nb * BK);
        }
        CP_COMMIT();

        const uint32_t stA = asu + (i % GSTAGES) * STG_F * 4 + aAddr0;
        const uint32_t stB = bsu + (i % GSTAGES) * STG_F * 4 + bAddr0;
#pragma unroll
        for (int ks = 0; ks < 2; ks++) {
            uint32_t a0[4], a1[4], bf[4][4];
            ldsm4(a0, stA + ks * 32);
            ldsm4(a1, stA + 16 * LDT * 4 + ks * 32);
#pragma unroll
            for (int grp = 0; grp < 4; grp++)
                ldsm4(bf[grp], stB + grp * 16 * LDT * 4 + ks * 32);
#pragma unroll
            for (int ni = 0; ni < 8; ni++) {
                int grp = ni >> 1, odd = ni & 1;
                mma_tf32(c[0][ni], a0, bf[grp][odd], bf[grp][2 + odd]);
                mma_tf32(c[1][ni], a1, bf[grp][odd], bf[grp][2 + odd]);
            }
        }
        __syncthreads();
    }

    // ---------------- epilogues ----------------
    if (MODE == 0) {
#pragma unroll
        for (int mi = 0; mi < 2; mi++) {
            int r0 = m0 + wm * 32 + mi * 16 + g;
#pragma unroll
            for (int ni = 0; ni < 8; ni++) {
                int cc = n0 + wn * 64 + ni * 8 + tg * 2;
                size_t o1 = (size_t)r0 * N + cc;
                size_t o2 = (size_t)(r0 + 8) * N + cc;
                float2 v1 = make_float2(c[mi][ni][0], c[mi][ni][1]);
                float2 v2 = make_float2(c[mi][ni][2], c[mi][ni][3]);
                if (res) {
                    float2 r1 = *reinterpret_cast<const float2*>(res + o1);
                    float2 r2 = *reinterpret_cast<const float2*>(res + o2);
                    v1.x += r1.x; v1.y += r1.y; v2.x += r2.x; v2.y += r2.y;
                }
                *reinterpret_cast<float2*>(C + o1) = v1;
                *reinterpret_cast<float2*>(C + o2) = v2;
            }
        }
    } else if (MODE == 1 || MODE == 2) {
        int h = (n0 + wn * 64) >> 6;
#pragma unroll
        for (int mi = 0; mi < 2; mi++) {
#pragma unroll
            for (int half = 0; half < 2; half++) {
                int r0 = m0 + wm * 32 + mi * 16 + g + half * 8;
                int bb = r0 >> 11, s = r0 & 2047;
                size_t base = (((size_t)(bb * NHEAD + h)) * SEQ + s) * 64;
                if (MODE == 2) {
#pragma unroll
                    for (int ni = 0; ni < 8; ni++) {
                        float2 v = make_float2(c[mi][ni][half*2], c[mi][ni][half*2+1]);
                        *reinterpret_cast<float2*>(C + base + ni * 8 + tg * 2) = v;
                    }
                } else {
#pragma unroll
                    for (int ni = 0; ni < 4; ni++) {
                        int dk0 = ni * 8 + tg * 2;
                        float2 o1, o2;
#pragma unroll
                        for (int j = 0; j < 2; j++) {
                            int dk = dk0 + j;
                            float x1 = c[mi][ni][half*2 + j];
                            float x2 = c[mi][ni+4][half*2 + j];
                            float cs = g_cos[s * 32 + dk];
                            float sn = g_sin[s * 32 + dk];
                            float v1 = x1 * cs - x2 * sn;
                            float v2 = x2 * cs + x1 * sn;
                            if (j == 0) { o1.x = v1; o2.x = v2; }
                            else        { o1.y = v1; o2.y = v2; }
                        }
                        *reinterpret_cast<float2*>(C + base + dk0)      = o1;
                        *reinterpret_cast<float2*>(C + base + dk0 + 32) = o2;
                    }
                }
            }
        }
    } else {  // MODE 3: SwiGLU — output width N/2, tf32-rounded
        const int NO = N >> 1;
#pragma unroll
        for (int mi = 0; mi < 2; mi++) {
            int r0 = m0 + wm * 32 + mi * 16 + g;
#pragma unroll
            for (int ni = 0; ni < 8; ni++) {
                int oc = (n0 + wn * 64 + ni * 8) / 2 + tg;
                float u1a = c[mi][ni][0], u2a = c[mi][ni][1];
                float u1b = c[mi][ni][2], u2b = c[mi][ni][3];
                C[(size_t)r0 * NO + oc]       = tf32r(u1a * (u2a / (1.0f + expf(-u2a))));
                C[(size_t)(r0 + 8) * NO + oc] = tf32r(u1b * (u2b / (1.0f + expf(-u2b))));
            }
        }
    }
}

// ----------------------------------------------------------------------------
// Flash attention, causal; parallel online softmax; tf32-rounded output.
// ----------------------------------------------------------------------------
__global__ __launch_bounds__(256) void flash_attn(const float* __restrict__ Q,
                                                  const float* __restrict__ K,
                                                  const float* __restrict__ V,
                                                  float* __restrict__ ctx) {
    int qt = blockIdx.x;
    int bh = blockIdx.y;
    int tid = threadIdx.x;
    int tx = tid & 15, ty = tid >> 4;

    __shared__ float Qs[64][64];
    __shared__ float KsT[64][33];
    __shared__ float Vs[32][64];
    __shared__ float Ss[64][33];
    __shared__ float rowm[64], rowl[64], rowsc[64];

    const size_t baseQ = ((size_t)bh * SEQ + (size_t)qt * 64) * DHEAD;
#pragma unroll
    for (int it = 0; it < 4; it++) {
        int idx = tid + it * 256;
        int r = idx >> 4, c4 = (idx & 15) * 4;
        *reinterpret_cast<float4*>(&Qs[r][c4]) =
            *reinterpret_cast<const float4*>(Q + baseQ + (size_t)r * 64 + c4);
    }
    if (tid < 64) { rowm[tid] = -1e30f; rowl[tid] = 0.f; }
    float o[4][4] = {};
    __syncthreads();

    int qbase = qt * 64;
    int ntile = 2 * (qt + 1);
    for (int kt = 0; kt < ntile; kt++) {
        int kb = kt * 32;
        const float* Kb = K + ((size_t)bh * SEQ + kb) * DHEAD;
        const float* Vb = V + ((size_t)bh * SEQ + kb) * DHEAD;
#pragma unroll
        for (int it = 0; it < 2; it++) {
            int idx = tid + it * 256;
            int r = idx >> 4, c4 = (idx & 15) * 4;
            float4 kv = *reinterpret_cast<const float4*>(Kb + (size_t)r * 64 + c4);
            KsT[c4 + 0][r] = kv.x; KsT[c4 + 1][r] = kv.y;
            KsT[c4 + 2][r] = kv.z; KsT[c4 + 3][r] = kv.w;
            *reinterpret_cast<float4*>(&Vs[r][c4]) =
                *reinterpret_cast<const float4*>(Vb + (size_t)r * 64 + c4);
        }
        __syncthreads();

        float sacc[4][2] = {};
#pragma unroll 8
        for (int kk = 0; kk < 64; kk++) {
            float q0 = Qs[ty * 4 + 0][kk], q1 = Qs[ty * 4 + 1][kk];
            float q2 = Qs[ty * 4 + 2][kk], q3 = Qs[ty * 4 + 3][kk];
            float k0 = KsT[kk][tx * 2 + 0], k1 = KsT[kk][tx * 2 + 1];
            sacc[0][0] += q0 * k0; sacc[0][1] += q0 * k1;
            sacc[1][0] += q1 * k0; sacc[1][1] += q1 * k1;
            sacc[2][0] += q2 * k0; sacc[2][1] += q2 * k1;
            sacc[3][0] += q3 * k0; sacc[3][1] += q3 * k1;
        }
#pragma unroll
        for (int i = 0; i < 4; i++)
#pragma unroll
            for (int j = 0; j < 2; j++) {
                int r = ty * 4 + i, c = tx * 2 + j;
                int qg = qbase + r, kg = kb + c;
                Ss[r][c] = (kg <= qg) ? sacc[i][j] * 0.125f : -1e9f;
            }
        __syncthreads();

        {
            int r = tid >> 2, q = tid & 3;
            float* Sr = &Ss[r][q * 8];
            float mx = fmaxf(fmaxf(fmaxf(Sr[0], Sr[1]), fmaxf(Sr[2], Sr[3])),
                             fmaxf(fmaxf(Sr[4], Sr[5]), fmaxf(Sr[6], Sr[7])));
            mx = fmaxf(mx, __shfl_xor_sync(0xffffffffu, mx, 1));
            mx = fmaxf(mx, __shfl_xor_sync(0xffffffffu, mx, 2));
            float mOld = rowm[r];
            float mn = fmaxf(mOld, mx);
            float l = 0.f;
#pragma unroll
            for (int c = 0; c < 8; c++) {
                float e = __expf(Sr[c] - mn);
                Sr[c] = e; l += e;
            }
            l += __shfl_xor_sync(0xffffffffu, l, 1);
            l += __shfl_xor_sync(0xffffffffu, l, 2);
            if (q == 0) {
                float sc = __expf(mOld - mn);
                rowsc[r] = sc;
                rowl[r] = rowl[r] * sc + l;
                rowm[r] = mn;
            }
        }
        __syncthreads();

#pragma unroll
        for (int i = 0; i < 4; i++) {
            float sc = rowsc[ty * 4 + i];
#pragma unroll
            for (int j = 0; j < 4; j++) o[i][j] *= sc;
        }
#pragma unroll 8
        for (int kk = 0; kk < 32; kk++) {
            float p0 = Ss[ty * 4 + 0][kk], p1 = Ss[ty * 4 + 1][kk];
            float p2 = Ss[ty * 4 + 2][kk], p3 = Ss[ty * 4 + 3][kk];
            float v0 = Vs[kk][tx * 4 + 0], v1 = Vs[kk][tx * 4 + 1];
            float v2 = Vs[kk][tx * 4 + 2], v3 = Vs[kk][tx * 4 + 3];
            o[0][0] += p0 * v0; o[0][1] += p0 * v1; o[0][2] += p0 * v2; o[0][3] += p0 * v3;
            o[1][0] += p1 * v0; o[1][1] += p1 * v1; o[1][2] += p1 * v2; o[1][3] += p1 * v3;
            o[2][0] += p2 * v0; o[2][1] += p2 * v1; o[2][2] += p2 * v2; o[2][3] += p2 * v3;
            o[3][0] += p3 * v0; o[3][1] += p3 * v1; o[3][2] += p3 * v2; o[3][3] += p3 * v3;
        }
        __syncthreads();
    }

    int b = bh >> 4, h = bh & 15;
#pragma unroll
    for (int i = 0; i < 4; i++) {
        int r = ty * 4 + i;
        size_t grow = (size_t)b * SEQ + qbase + r;
        float invl = 1.0f / rowl[r];
#pragma unroll
        for (int j = 0; j < 4; j++)
            ctx[grow * DMODEL + h * 64 + tx * 4 + j] = tf32r(o[i][j] * invl);
    }
}

// ----------------------------------------------------------------------------
// Launch
// ----------------------------------------------------------------------------
extern "C" void kernel_launch(void* const* d_in, const int* in_sizes, int n_in,
                              void* d_out, int out_size) {
    const float* x  = (const float*)d_in[0];
    const float* wq = (const float*)d_in[2];
    const float* wk = (const float*)d_in[3];
    const float* wv = (const float*)d_in[4];
    const float* wo = (const float*)d_in[5];
    const float* w1 = (const float*)d_in[6];
    const float* w2 = (const float*)d_in[7];
    const float* g1 = (const float*)d_in[8];
    const float* g2 = (const float*)d_in[9];
    float* out = (float*)d_out;

    static float *p_h=nullptr,*p_q=nullptr,*p_k=nullptr,*p_v=nullptr,
                 *p_ctx=nullptr,*p_x2=nullptr,*p_ffn=nullptr,
                 *p_wq=nullptr,*p_wk=nullptr,*p_wv=nullptr,*p_wo=nullptr,
                 *p_w1=nullptr,*p_w2=nullptr;
    if (!p_h) {
        cudaGetSymbolAddress((void**)&p_h,   g_h);
        cudaGetSymbolAddress((void**)&p_q,   g_q);
        cudaGetSymbolAddress((void**)&p_k,   g_k);
        cudaGetSymbolAddress((void**)&p_v,   g_v);
        cudaGetSymbolAddress((void**)&p_ctx, g_ctx);
        cudaGetSymbolAddress((void**)&p_x2,  g_x2);
        cudaGetSymbolAddress((void**)&p_ffn, g_ffn);
        cudaGetSymbolAddress((void**)&p_wq,  g_wq_r);
        cudaGetSymbolAddress((void**)&p_wk,  g_wk_r);
        cudaGetSymbolAddress((void**)&p_wv,  g_wv_r);
        cudaGetSymbolAddress((void**)&p_wo,  g_wo_r);
        cudaGetSymbolAddress((void**)&p_w1,  g_w1_r);
        cudaGetSymbolAddress((void**)&p_w2,  g_w2_r);
        cudaFuncSetAttribute(gemm_mma<0>, cudaFuncAttributeMaxDynamicSharedMemorySize, GEMM_SMEM);
        cudaFuncSetAttribute(gemm_mma<1>, cudaFuncAttributeMaxDynamicSharedMemorySize, GEMM_SMEM);
        cudaFuncSetAttribute(gemm_mma<2>, cudaFuncAttributeMaxDynamicSharedMemorySize, GEMM_SMEM);
        cudaFuncSetAttribute(gemm_mma<3>, cudaFuncAttributeMaxDynamicSharedMemorySize, GEMM_SMEM);
    }

    build_rope_table<<<(SEQ * 32 + 255) / 256, 256>>>();

    // tf32-round weights into scratch (w1 also row-permuted for SwiGLU fusion)
    round_tf32_k<<<(DMODEL*DMODEL/4 + 255)/256, 256>>>((const float4*)wq, (float4*)p_wq, DMODEL*DMODEL/4);
    round_tf32_k<<<(DMODEL*DMODEL/4 + 255)/256, 256>>>((const float4*)wk, (float4*)p_wk, DMODEL*DMODEL/4);
    round_tf32_k<<<(DMODEL*DMODEL/4 + 255)/256, 256>>>((const float4*)wv, (float4*)p_wv, DMODEL*DMODEL/4);
    round_tf32_k<<<(DMODEL*DMODEL/4 + 255)/256, 256>>>((const float4*)wo, (float4*)p_wo, DMODEL*DMODEL/4);
    round_perm_w1<<<(2*DFF*(DMODEL/4) + 255)/256, 256>>>((const float4*)w1, (float4*)p_w1);
    round_tf32_k<<<(DMODEL*DFF/4 + 255)/256, 256>>>((const float4*)w2, (float4*)p_w2, DMODEL*DFF/4);

    // --- attention sublayer ---
    rmsnorm_k<<<ROWS, 256>>>(x, g1, p_h);

    dim3 gproj(DMODEL / 128, ROWS / 128);   // (8, 32)
    gemm_mma<1><<<gproj, 256, GEMM_SMEM>>>(p_h, p_wq, nullptr, p_q, ROWS, DMODEL, DMODEL);
    gemm_mma<1><<<gproj, 256, GEMM_SMEM>>>(p_h, p_wk, nullptr, p_k, ROWS, DMODEL, DMODEL);
    gemm_mma<2><<<gproj, 256, GEMM_SMEM>>>(p_h, p_wv, nullptr, p_v, ROWS, DMODEL, DMODEL);

    flash_attn<<<dim3(SEQ / 64, BATCH * NHEAD), 256>>>(p_q, p_k, p_v, p_ctx);

    gemm_mma<0><<<gproj, 256, GEMM_SMEM>>>(p_ctx, p_wo, x, p_x2, ROWS, DMODEL, DMODEL);

    // --- FFN sublayer ---
    rmsnorm_k<<<ROWS, 256>>>(p_x2, g2, p_h);
    dim3 gup(2 * DFF / 128, ROWS / 128);    // (64, 32)
    gemm_mma<3><<<gup, 256, GEMM_SMEM>>>(p_h, p_w1, nullptr, p_ffn, ROWS, 2 * DFF, DMODEL);
    dim3 gdown(DMODEL / 128, ROWS / 128);   // (8, 32)
    gemm_mma<0><<<gdown, 256, GEMM_SMEM>>>(p_ffn, p_w2, p_x2, out, ROWS, DMODEL, DFF);
}

// round 7
// speedup vs baseline: 3.3351x; 1.3500x over previous
#include <cuda_runtime.h>
#include <cuda_bf16.h>
#include <math.h>
#include <stdint.h>

// Problem constants
#define BATCH 2
#define SEQ   2048
#define DMODEL 1024
#define NHEAD 16
#define DHEAD 64
#define DFF   4096
#define ROWS  (BATCH*SEQ)   // 4096

// ----------------------------------------------------------------------------
// Scratch (device globals; no allocations allowed)
// ----------------------------------------------------------------------------
__device__ float g_h   [(size_t)ROWS*DMODEL];
__device__ float g_q   [(size_t)ROWS*DMODEL];
__device__ float g_k   [(size_t)ROWS*DMODEL];
__device__ float g_v   [(size_t)ROWS*DMODEL];
__device__ float g_ctx [(size_t)ROWS*DMODEL];
__device__ float g_x2  [(size_t)ROWS*DMODEL];
__device__ float g_ffn [(size_t)ROWS*DFF];
__device__ float g_cos [SEQ*32];
__device__ float g_sin [SEQ*32];
// tf32-rounded weights
__device__ float g_wq_r[(size_t)DMODEL*DMODEL];
__device__ float g_wk_r[(size_t)DMODEL*DMODEL];
__device__ float g_wv_r[(size_t)DMODEL*DMODEL];
__device__ float g_wo_r[(size_t)DMODEL*DMODEL];
__device__ float g_w1_r[(size_t)2*DFF*DMODEL];   // row-permuted: u1/u2 interleaved
__device__ float g_w2_r[(size_t)DMODEL*DFF];

// ----------------------------------------------------------------------------
// Helpers
// ----------------------------------------------------------------------------
__device__ __forceinline__ float tf32r(float x) {
    uint32_t u;
    asm("cvt.rna.tf32.f32 %0, %1;" : "=r"(u) : "f"(x));
    return __uint_as_float(u);
}
__device__ __forceinline__ uint32_t smem_u32(const void* p) {
    uint32_t a;
    asm("{ .reg .u64 t; cvta.to.shared.u64 t, %1; cvt.u32.u64 %0, t; }" : "=r"(a) : "l"(p));
    return a;
}
__device__ __forceinline__ void cp16(uint32_t dst, const void* src) {
    asm volatile("cp.async.ca.shared.global [%0], [%1], 16;" :: "r"(dst), "l"(src) : "memory");
}
#define CP_COMMIT() asm volatile("cp.async.commit_group;" ::: "memory")
#define CP_WAIT1()  asm volatile("cp.async.wait_group 1;" ::: "memory")
#define CP_WAIT0()  asm volatile("cp.async.wait_group 0;" ::: "memory")

__device__ __forceinline__ void mma_tf32(float* c, const uint32_t* a, uint32_t b0, uint32_t b1) {
    asm volatile("mma.sync.aligned.m16n8k8.row.col.f32.tf32.tf32.f32 "
                 "{%0,%1,%2,%3}, {%4,%5,%6,%7}, {%8,%9}, {%0,%1,%2,%3};"
                 : "+f"(c[0]), "+f"(c[1]), "+f"(c[2]), "+f"(c[3])
                 : "r"(a[0]), "r"(a[1]), "r"(a[2]), "r"(a[3]), "r"(b0), "r"(b1));
}
__device__ __forceinline__ void ldsm4(uint32_t* r, uint32_t addr) {
    asm volatile("ldmatrix.sync.aligned.m8n8.x4.shared.b16 {%0,%1,%2,%3}, [%4];"
                 : "=r"(r[0]), "=r"(r[1]), "=r"(r[2]), "=r"(r[3]) : "r"(addr));
}

// ----------------------------------------------------------------------------
// RoPE table
// ----------------------------------------------------------------------------
__global__ void build_rope_table() {
    int idx = blockIdx.x * blockDim.x + threadIdx.x;
    if (idx >= SEQ * 32) return;
    int s = idx / 32, j = idx % 32;
    double invf = exp(-(double)j * (9.210340371976184 / 32.0));
    double a = (double)s * invf;
    g_cos[idx] = (float)cos(a);
    g_sin[idx] = (float)sin(a);
}

// ----------------------------------------------------------------------------
// tf32 rounding of weights
// ----------------------------------------------------------------------------
__global__ __launch_bounds__(256) void round_tf32_k(const float4* __restrict__ in,
                                                    float4* __restrict__ out, int n4) {
    int i = blockIdx.x * 256 + threadIdx.x;
    if (i >= n4) return;
    float4 v = in[i];
    v.x = tf32r(v.x); v.y = tf32r(v.y); v.z = tf32r(v.z); v.w = tf32r(v.w);
    out[i] = v;
}

// w1 round + row-permute: dst row 2j <- src j (u1), dst row 2j+1 <- src DFF+j (u2)
__global__ __launch_bounds__(256) void round_perm_w1(const float4* __restrict__ in,
                                                     float4* __restrict__ out) {
    int i = blockIdx.x * 256 + threadIdx.x;
    const int C4 = DMODEL / 4;
    if (i >= 2 * DFF * C4) return;
    int row = i / C4, c = i % C4;
    int src = (row & 1) ? (DFF + (row >> 1)) : (row >> 1);
    float4 v = in[(size_t)src * C4 + c];
    v.x = tf32r(v.x); v.y = tf32r(v.y); v.z = tf32r(v.z); v.w = tf32r(v.w);
    out[i] = v;
}

// ----------------------------------------------------------------------------
// RMSNorm (tf32-rounded output: feeds tensor-core GEMMs)
// ----------------------------------------------------------------------------
__global__ __launch_bounds__(256) void rmsnorm_k(const float* __restrict__ x,
                                                 const float* __restrict__ g,
                                                 float* __restrict__ o) {
    int row = blockIdx.x;
    const float* xr = x + (size_t)row * DMODEL;
    float ss = 0.f;
    for (int c = threadIdx.x; c < DMODEL; c += 256) { float v = xr[c]; ss += v * v; }
    __shared__ float sm[8];
    for (int off = 16; off; off >>= 1) ss += __shfl_down_sync(0xffffffffu, ss, off);
    if ((threadIdx.x & 31) == 0) sm[threadIdx.x >> 5] = ss;
    __syncthreads();
    if (threadIdx.x < 8) {
        float v = sm[threadIdx.x];
        for (int off = 4; off; off >>= 1) v += __shfl_down_sync(0xffu, v, off);
        if (threadIdx.x == 0) sm[0] = v;
    }
    __syncthreads();
    float inv = 1.0f / sqrtf(sm[0] / (float)DMODEL + 1e-6f);
    float* orow = o + (size_t)row * DMODEL;
    for (int c = threadIdx.x; c < DMODEL; c += 256) orow[c] = tf32r(xr[c] * inv * g[c]);
}

// ----------------------------------------------------------------------------
// TF32 mma.sync GEMM with ldmatrix fragments and fused epilogues.
// C[M,N] = A[M,K] @ B[N,K]^T.  BM=128 BN=128 BK=16, 256 thr, warps 4m x 2n.
// MODE 0: plain store (+res).  MODE 1: RoPE + head-transpose (tf32r).
// MODE 2: head-transpose only (tf32r). MODE 3: SwiGLU pairs (w1 row-permuted).
// ----------------------------------------------------------------------------
#define BK 16
#define LDT 20
#define STG_F (128*LDT)
#define GSTAGES 3
#define GEMM_SMEM (GSTAGES*2*STG_F*4)   // 61440 bytes

template<int MODE>
__global__ void __launch_bounds__(256, 2) gemm_mma(
    const float* __restrict__ A, const float* __restrict__ B,
    const float* __restrict__ res, float* __restrict__ C,
    int M, int N, int K)
{
    extern __shared__ float smf[];
    float* As = smf;
    float* Bs = smf + GSTAGES * STG_F;
    const uint32_t asu = smem_u32(As);
    const uint32_t bsu = smem_u32(Bs);

    const int tid = threadIdx.x;
    const int wid = tid >> 5, lane = tid & 31;
    const int wm = wid & 3, wn = wid >> 2;       // warp grid 4x2
    const int g = lane >> 2, tg = lane & 3;
    const int m0 = blockIdx.y * 128, n0 = blockIdx.x * 128;

    const int ldr0 = tid >> 2;
    const int ldc0 = (tid & 3) * 4;
    const float* Ag = A + (size_t)(m0 + ldr0) * K + ldc0;
    const float* Bg = B + (size_t)(n0 + ldr0) * K + ldc0;
    const float* Ag2 = Ag + (size_t)64 * K;
    const float* Bg2 = Bg + (size_t)64 * K;

    const int niter = K >> 4;

#pragma unroll
    for (int s = 0; s < GSTAGES - 1; s++) {
        uint32_t da = asu + (s * STG_F + ldr0 * LDT + ldc0) * 4;
        uint32_t db = bsu + (s * STG_F + ldr0 * LDT + ldc0) * 4;
        cp16(da,                Ag  + s * BK);
        cp16(da + 64 * LDT * 4, Ag2 + s * BK);
        cp16(db,                Bg  + s * BK);
        cp16(db + 64 * LDT * 4, Bg2 + s * BK);
        CP_COMMIT();
    }

    float c[2][8][4] = {};

    const int r15 = lane & 15;
    const int ch16 = (lane >> 4) << 4;
    const uint32_t aAddr0 = (uint32_t)((wm * 32 + r15) * LDT * 4 + ch16);
    const uint32_t bAddr0 = (uint32_t)((wn * 64 + r15) * LDT * 4 + ch16);

    for (int i = 0; i < niter; i++) {
        CP_WAIT1();
        __syncthreads();

        int nb = i + GSTAGES - 1;
        if (nb < niter) {
            int s = nb % GSTAGES;
            uint32_t da = asu + (s * STG_F + ldr0 * LDT + ldc0) * 4;
            uint32_t db = bsu + (s * STG_F + ldr0 * LDT + ldc0) * 4;
            cp16(da,                Ag  + nb * BK);
            cp16(da + 64 * LDT * 4, Ag2 + nb * BK);
            cp16(db,                Bg  + nb * BK);
            cp16(db + 64 * LDT * 4, Bg2 + nb * BK);
        }
        CP_COMMIT();

        const uint32_t stA = asu + (i % GSTAGES) * STG_F * 4 + aAddr0;
        const uint32_t stB = bsu + (i % GSTAGES) * STG_F * 4 + bAddr0;
#pragma unroll
        for (int ks = 0; ks < 2; ks++) {
            uint32_t a0[4], a1[4], bf[4][4];
            ldsm4(a0, stA + ks * 32);
            ldsm4(a1, stA + 16 * LDT * 4 + ks * 32);
#pragma unroll
            for (int grp = 0; grp < 4; grp++)
                ldsm4(bf[grp], stB + grp * 16 * LDT * 4 + ks * 32);
#pragma unroll
            for (int ni = 0; ni < 8; ni++) {
                int grp = ni >> 1, odd = ni & 1;
                mma_tf32(c[0][ni], a0, bf[grp][odd], bf[grp][2 + odd]);
                mma_tf32(c[1][ni], a1, bf[grp][odd], bf[grp][2 + odd]);
            }
        }
        __syncthreads();
    }

    // ---------------- epilogues ----------------
    if (MODE == 0) {
#pragma unroll
        for (int mi = 0; mi < 2; mi++) {
            int r0 = m0 + wm * 32 + mi * 16 + g;
#pragma unroll
            for (int ni = 0; ni < 8; ni++) {
                int cc = n0 + wn * 64 + ni * 8 + tg * 2;
                size_t o1 = (size_t)r0 * N + cc;
                size_t o2 = (size_t)(r0 + 8) * N + cc;
                float2 v1 = make_float2(c[mi][ni][0], c[mi][ni][1]);
                float2 v2 = make_float2(c[mi][ni][2], c[mi][ni][3]);
                if (res) {
                    float2 r1 = *reinterpret_cast<const float2*>(res + o1);
                    float2 r2 = *reinterpret_cast<const float2*>(res + o2);
                    v1.x += r1.x; v1.y += r1.y; v2.x += r2.x; v2.y += r2.y;
                }
                *reinterpret_cast<float2*>(C + o1) = v1;
                *reinterpret_cast<float2*>(C + o2) = v2;
            }
        }
    } else if (MODE == 1 || MODE == 2) {
        int h = (n0 + wn * 64) >> 6;
#pragma unroll
        for (int mi = 0; mi < 2; mi++) {
#pragma unroll
            for (int half = 0; half < 2; half++) {
                int r0 = m0 + wm * 32 + mi * 16 + g + half * 8;
                int bb = r0 >> 11, s = r0 & 2047;
                size_t base = (((size_t)(bb * NHEAD + h)) * SEQ + s) * 64;
                if (MODE == 2) {
#pragma unroll
                    for (int ni = 0; ni < 8; ni++) {
                        float2 v = make_float2(tf32r(c[mi][ni][half*2]),
                                               tf32r(c[mi][ni][half*2+1]));
                        *reinterpret_cast<float2*>(C + base + ni * 8 + tg * 2) = v;
                    }
                } else {
#pragma unroll
                    for (int ni = 0; ni < 4; ni++) {
                        int dk0 = ni * 8 + tg * 2;
                        float2 o1, o2;
#pragma unroll
                        for (int j = 0; j < 2; j++) {
                            int dk = dk0 + j;
                            float x1 = c[mi][ni][half*2 + j];
                            float x2 = c[mi][ni+4][half*2 + j];
                            float cs = g_cos[s * 32 + dk];
                            float sn = g_sin[s * 32 + dk];
                            float v1 = tf32r(x1 * cs - x2 * sn);
                            float v2 = tf32r(x2 * cs + x1 * sn);
                            if (j == 0) { o1.x = v1; o2.x = v2; }
                            else        { o1.y = v1; o2.y = v2; }
                        }
                        *reinterpret_cast<float2*>(C + base + dk0)      = o1;
                        *reinterpret_cast<float2*>(C + base + dk0 + 32) = o2;
                    }
                }
            }
        }
    } else {  // MODE 3: SwiGLU — output width N/2, tf32-rounded
        const int NO = N >> 1;
#pragma unroll
        for (int mi = 0; mi < 2; mi++) {
            int r0 = m0 + wm * 32 + mi * 16 + g;
#pragma unroll
            for (int ni = 0; ni < 8; ni++) {
                int oc = (n0 + wn * 64 + ni * 8) / 2 + tg;
                float u1a = c[mi][ni][0], u2a = c[mi][ni][1];
                float u1b = c[mi][ni][2], u2b = c[mi][ni][3];
                C[(size_t)r0 * NO + oc]       = tf32r(u1a * (u2a / (1.0f + expf(-u2a))));
                C[(size_t)(r0 + 8) * NO + oc] = tf32r(u1b * (u2b / (1.0f + expf(-u2b))));
            }
        }
    }
}

// ----------------------------------------------------------------------------
// Flash attention on tensor cores (tf32 mma.sync), causal, 64x64 tiles.
// 256 threads, 8 warps (4m x 2n). K/V double-buffered via cp.async.
// Dynamic smem: Qs + 2*Ks + 2*Vs + Ps (64x68 each) + row stats.
// ----------------------------------------------------------------------------
#define FA_LDA 68
#define FA_TILE (64*FA_LDA)
#define FA_SMEM ((6*FA_TILE + 192)*4)   // 105984 bytes

__global__ void __launch_bounds__(256, 2) flash_attn_tc(
    const float* __restrict__ Q, const float* __restrict__ Kg,
    const float* __restrict__ Vg, float* __restrict__ ctx)
{
    extern __shared__ float fs[];
    float* Qs   = fs;
    float* Ks   = fs + FA_TILE;         // 2 buffers
    float* Vs   = fs + 3 * FA_TILE;     // 2 buffers
    float* Ps   = fs + 5 * FA_TILE;
    float* rowm = fs + 6 * FA_TILE;
    float* rowl = rowm + 64;
    float* rowsc = rowl + 64;

    const uint32_t qsu = smem_u32(Qs);
    const uint32_t ksu = smem_u32(Ks);
    const uint32_t vsu = smem_u32(Vs);
    const uint32_t psu = smem_u32(Ps);

    const int qt = (int)gridDim.x - 1 - (int)blockIdx.x;   // heavy blocks first
    const int bh = blockIdx.y;
    const int tid = threadIdx.x;
    const int wid = tid >> 5, lane = tid & 31;
    const int wm = wid & 3, wn = wid >> 2;
    const int g = lane >> 2, tg = lane & 3;
    const int r15 = lane & 15;
    const int ch16 = (lane >> 4) << 4;

    const int ldr = tid >> 4;            // 0..15 (row block of 16 rows? no: row = idx>>4)
    const int ldc4 = (tid & 15) * 4;

    // Load Q tile (straight copy with padded rows)
    const size_t baseQ = ((size_t)bh * SEQ + (size_t)qt * 64) * DHEAD;
#pragma unroll
    for (int it = 0; it < 4; it++) {
        int idx = tid + it * 256;
        int r = idx >> 4, c4 = (idx & 15) * 4;
        *reinterpret_cast<float4*>(Qs + r * FA_LDA + c4) =
            *reinterpret_cast<const float4*>(Q + baseQ + (size_t)r * DHEAD + c4);
    }
    if (tid < 64) { rowm[tid] = -1e30f; rowl[tid] = 0.f; }

    const int ntile = qt + 1;
    const int qbase = qt * 64;

    // prefetch kt=0 into buffer 0
    {
        const float* Kb = Kg + ((size_t)bh * SEQ) * DHEAD;
        const float* Vb = Vg + ((size_t)bh * SEQ) * DHEAD;
#pragma unroll
        for (int it = 0; it < 4; it++) {
            int idx = tid + it * 256;
            int r = idx >> 4, c4 = (idx & 15) * 4;
            cp16(ksu + (r * FA_LDA + c4) * 4, Kb + (size_t)r * DHEAD + c4);
            cp16(vsu + (r * FA_LDA + c4) * 4, Vb + (size_t)r * DHEAD + c4);
        }
        CP_COMMIT();
    }

    float co[4][4] = {};

    for (int kt = 0; kt < ntile; kt++) {
        const int buf = kt & 1;
        if (kt + 1 < ntile) {
            const float* Kb = Kg + ((size_t)bh * SEQ + (size_t)(kt+1) * 64) * DHEAD;
            const float* Vb = Vg + ((size_t)bh * SEQ + (size_t)(kt+1) * 64) * DHEAD;
            uint32_t kd = ksu + ((buf ^ 1) * FA_TILE) * 4;
            uint32_t vd = vsu + ((buf ^ 1) * FA_TILE) * 4;
#pragma unroll
            for (int it = 0; it < 4; it++) {
                int idx = tid + it * 256;
                int r = idx >> 4, c4 = (idx & 15) * 4;
                cp16(kd + (r * FA_LDA + c4) * 4, Kb + (size_t)r * DHEAD + c4);
                cp16(vd + (r * FA_LDA + c4) * 4, Vb + (size_t)r * DHEAD + c4);
            }
            CP_COMMIT();
            CP_WAIT1();
        } else {
            CP_WAIT0();
        }
        __syncthreads();   // K/V[buf] visible to all

        // ---- S = Q @ K^T  (warp: 16 rows x 32 cols) ----
        float cs_[4][4] = {};
        {
            const uint32_t aQ = qsu + ((wm * 16 + r15) * FA_LDA) * 4 + ch16;
            const uint32_t bK = ksu + (buf * FA_TILE + (wn * 32 + r15) * FA_LDA) * 4 + ch16;
#pragma unroll
            for (int ks = 0; ks < 8; ks++) {
                uint32_t qa[4], k0f[4], k1f[4];
                ldsm4(qa, aQ + ks * 32);
                ldsm4(k0f, bK + ks * 32);
                ldsm4(k1f, bK + 16 * FA_LDA * 4 + ks * 32);
                mma_tf32(cs_[0], qa, k0f[0], k0f[2]);
                mma_tf32(cs_[1], qa, k0f[1], k0f[3]);
                mma_tf32(cs_[2], qa, k1f[0], k1f[2]);
                mma_tf32(cs_[3], qa, k1f[1], k1f[3]);
            }
        }

        // ---- mask + scale -> Ps ----
        {
            const int kb = kt * 64;
#pragma unroll
            for (int ni = 0; ni < 4; ni++) {
                int cc = wn * 32 + ni * 8 + tg * 2;
#pragma unroll
                for (int half = 0; half < 2; half++) {
                    int r = wm * 16 + g + half * 8;
                    int qg = qbase + r;
                    float v0 = cs_[ni][half*2]   * 0.125f;
                    float v1 = cs_[ni][half*2+1] * 0.125f;
                    Ps[r * FA_LDA + cc]     = (kb + cc     <= qg) ? v0 : -1e9f;
                    Ps[r * FA_LDA + cc + 1] = (kb + cc + 1 <= qg) ? v1 : -1e9f;
                }
            }
        }
        __syncthreads();

        // ---- online softmax (4 threads per row, 16 cols each) ----
        {
            int r = tid >> 2, q = tid & 3;
            float* Sr = &Ps[r * FA_LDA + q * 16];
            float mx = -1e30f;
#pragma unroll
            for (int c = 0; c < 16; c++) mx = fmaxf(mx, Sr[c]);
            mx = fmaxf(mx, __shfl_xor_sync(0xffffffffu, mx, 1));
            mx = fmaxf(mx, __shfl_xor_sync(0xffffffffu, mx, 2));
            float mOld = rowm[r];
            float mn = fmaxf(mOld, mx);
            float l = 0.f;
#pragma unroll
            for (int c = 0; c < 16; c++) {
                float e = __expf(Sr[c] - mn);
                Sr[c] = tf32r(e); l += e;
            }
            l += __shfl_xor_sync(0xffffffffu, l, 1);
            l += __shfl_xor_sync(0xffffffffu, l, 2);
            if (q == 0) {
                float sc = __expf(mOld - mn);
                rowsc[r] = sc;
                rowl[r] = rowl[r] * sc + l;
                rowm[r] = mn;
            }
        }
        __syncthreads();

        // ---- rescale O, then O += P @ V ----
        {
            float scg  = rowsc[wm * 16 + g];
            float scg8 = rowsc[wm * 16 + g + 8];
#pragma unroll
            for (int ni = 0; ni < 4; ni++) {
                co[ni][0] *= scg;  co[ni][1] *= scg;
                co[ni][2] *= scg8; co[ni][3] *= scg8;
            }
            const uint32_t aP = psu + ((wm * 16 + r15) * FA_LDA) * 4 + ch16;
            const float* Vb = Vs + buf * FA_TILE;
#pragma unroll
            for (int ks = 0; ks < 8; ks++) {
                uint32_t pa[4];
                ldsm4(pa, aP + ks * 32);
                const float* vrow = Vb + (ks * 8 + tg) * FA_LDA;
#pragma unroll
                for (int ni = 0; ni < 4; ni++) {
                    int n0g = wn * 32 + ni * 8 + g;
                    uint32_t b0 = __float_as_uint(vrow[n0g]);
                    uint32_t b1 = __float_as_uint(vrow[4 * FA_LDA + n0g]);
                    mma_tf32(co[ni], pa, b0, b1);
                }
            }
        }
        __syncthreads();   // protect Ps / Vs[buf] before overwrite
    }

    // ---- final write: divide by l, scatter to [B,S,D] with tf32 rounding ----
    {
        int b = bh >> 4, h = bh & 15;
        float il_g  = 1.0f / rowl[wm * 16 + g];
        float il_g8 = 1.0f / rowl[wm * 16 + g + 8];
#pragma unroll
        for (int half = 0; half < 2; half++) {
            int r = wm * 16 + g + half * 8;
            float il = half ? il_g8 : il_g;
            size_t grow = ((size_t)b * SEQ + qbase + r) * DMODEL + h * 64;
#pragma unroll
            for (int ni = 0; ni < 4; ni++) {
                int d0 = wn * 32 + ni * 8 + tg * 2;
                float2 v = make_float2(tf32r(co[ni][half*2]   * il),
                                       tf32r(co[ni][half*2+1] * il));
                *reinterpret_cast<float2*>(ctx + grow + d0) = v;
            }
        }
    }
}

// ----------------------------------------------------------------------------
// Launch
// ----------------------------------------------------------------------------
extern "C" void kernel_launch(void* const* d_in, const int* in_sizes, int n_in,
                              void* d_out, int out_size) {
    const float* x  = (const float*)d_in[0];
    const float* wq = (const float*)d_in[2];
    const float* wk = (const float*)d_in[3];
    const float* wv = (const float*)d_in[4];
    const float* wo = (const float*)d_in[5];
    const float* w1 = (const float*)d_in[6];
    const float* w2 = (const float*)d_in[7];
    const float* g1 = (const float*)d_in[8];
    const float* g2 = (const float*)d_in[9];
    float* out = (float*)d_out;

    static float *p_h=nullptr,*p_q=nullptr,*p_k=nullptr,*p_v=nullptr,
                 *p_ctx=nullptr,*p_x2=nullptr,*p_ffn=nullptr,
                 *p_wq=nullptr,*p_wk=nullptr,*p_wv=nullptr,*p_wo=nullptr,
                 *p_w1=nullptr,*p_w2=nullptr;
    if (!p_h) {
        cudaGetSymbolAddress((void**)&p_h,   g_h);
        cudaGetSymbolAddress((void**)&p_q,   g_q);
        cudaGetSymbolAddress((void**)&p_k,   g_k);
        cudaGetSymbolAddress((void**)&p_v,   g_v);
        cudaGetSymbolAddress((void**)&p_ctx, g_ctx);
        cudaGetSymbolAddress((void**)&p_x2,  g_x2);
        cudaGetSymbolAddress((void**)&p_ffn, g_ffn);
        cudaGetSymbolAddress((void**)&p_wq,  g_wq_r);
        cudaGetSymbolAddress((void**)&p_wk,  g_wk_r);
        cudaGetSymbolAddress((void**)&p_wv,  g_wv_r);
        cudaGetSymbolAddress((void**)&p_wo,  g_wo_r);
        cudaGetSymbolAddress((void**)&p_w1,  g_w1_r);
        cudaGetSymbolAddress((void**)&p_w2,  g_w2_r);
        cudaFuncSetAttribute(gemm_mma<0>, cudaFuncAttributeMaxDynamicSharedMemorySize, GEMM_SMEM);
        cudaFuncSetAttribute(gemm_mma<1>, cudaFuncAttributeMaxDynamicSharedMemorySize, GEMM_SMEM);
        cudaFuncSetAttribute(gemm_mma<2>, cudaFuncAttributeMaxDynamicSharedMemorySize, GEMM_SMEM);
        cudaFuncSetAttribute(gemm_mma<3>, cudaFuncAttributeMaxDynamicSharedMemorySize, GEMM_SMEM);
        cudaFuncSetAttribute(flash_attn_tc, cudaFuncAttributeMaxDynamicSharedMemorySize, FA_SMEM);
    }

    build_rope_table<<<(SEQ * 32 + 255) / 256, 256>>>();

    // tf32-round weights into scratch (w1 also row-permuted for SwiGLU fusion)
    round_tf32_k<<<(DMODEL*DMODEL/4 + 255)/256, 256>>>((const float4*)wq, (float4*)p_wq, DMODEL*DMODEL/4);
    round_tf32_k<<<(DMODEL*DMODEL/4 + 255)/256, 256>>>((const float4*)wk, (float4*)p_wk, DMODEL*DMODEL/4);
    round_tf32_k<<<(DMODEL*DMODEL/4 + 255)/256, 256>>>((const float4*)wv, (float4*)p_wv, DMODEL*DMODEL/4);
    round_tf32_k<<<(DMODEL*DMODEL/4 + 255)/256, 256>>>((const float4*)wo, (float4*)p_wo, DMODEL*DMODEL/4);
    round_perm_w1<<<(2*DFF*(DMODEL/4) + 255)/256, 256>>>((const float4*)w1, (float4*)p_w1);
    round_tf32_k<<<(DMODEL*DFF/4 + 255)/256, 256>>>((const float4*)w2, (float4*)p_w2, DMODEL*DFF/4);

    // --- attention sublayer ---
    rmsnorm_k<<<ROWS, 256>>>(x, g1, p_h);

    dim3 gproj(DMODEL / 128, ROWS / 128);   // (8, 32)
    gemm_mma<1><<<gproj, 256, GEMM_SMEM>>>(p_h, p_wq, nullptr, p_q, ROWS, DMODEL, DMODEL);
    gemm_mma<1><<<gproj, 256, GEMM_SMEM>>>(p_h, p_wk, nullptr, p_k, ROWS, DMODEL, DMODEL);
    gemm_mma<2><<<gproj, 256, GEMM_SMEM>>>(p_h, p_wv, nullptr, p_v, ROWS, DMODEL, DMODEL);

    flash_attn_tc<<<dim3(SEQ / 64, BATCH * NHEAD), 256, FA_SMEM>>>(p_q, p_k, p_v, p_ctx);

    gemm_mma<0><<<gproj, 256, GEMM_SMEM>>>(p_ctx, p_wo, x, p_x2, ROWS, DMODEL, DMODEL);

    // --- FFN sublayer ---
    rmsnorm_k<<<ROWS, 256>>>(p_x2, g2, p_h);
    dim3 gup(2 * DFF / 128, ROWS / 128);    // (64, 32)
    gemm_mma<3><<<gup, 256, GEMM_SMEM>>>(p_h, p_w1, nullptr, p_ffn, ROWS, 2 * DFF, DMODEL);
    dim3 gdown(DMODEL / 128, ROWS / 128);   // (8, 32)
    gemm_mma<0><<<gdown, 256, GEMM_SMEM>>>(p_ffn, p_w2, p_x2, out, ROWS, DMODEL, DFF);
}

// round 8
// speedup vs baseline: 3.5614x; 1.0679x over previous
#include <cuda_runtime.h>
#include <cuda_bf16.h>
#include <math.h>
#include <stdint.h>

// Problem constants
#define BATCH 2
#define SEQ   2048
#define DMODEL 1024
#define NHEAD 16
#define DHEAD 64
#define DFF   4096
#define ROWS  (BATCH*SEQ)   // 4096

// ----------------------------------------------------------------------------
// Scratch (device globals; no allocations allowed)
// ----------------------------------------------------------------------------
__device__ float g_h   [(size_t)ROWS*DMODEL];
__device__ float g_q   [(size_t)ROWS*DMODEL];
__device__ float g_k   [(size_t)ROWS*DMODEL];
__device__ float g_v   [(size_t)ROWS*DMODEL];
__device__ float g_ctx [(size_t)ROWS*DMODEL];
__device__ float g_x2  [(size_t)ROWS*DMODEL];
__device__ float g_ffn [(size_t)ROWS*DFF];
__device__ float g_cos [SEQ*32];
__device__ float g_sin [SEQ*32];
__device__ float g_wqkv[(size_t)3*DMODEL*DMODEL];   // concat wq|wk|wv
__device__ float g_w1p [(size_t)2*DFF*DMODEL];      // w1 row-permuted (u1/u2 interleaved)

// ----------------------------------------------------------------------------
// Helpers
// ----------------------------------------------------------------------------
__device__ __forceinline__ uint32_t smem_u32(const void* p) {
    uint32_t a;
    asm("{ .reg .u64 t; cvta.to.shared.u64 t, %1; cvt.u32.u64 %0, t; }" : "=r"(a) : "l"(p));
    return a;
}
__device__ __forceinline__ void cp16(uint32_t dst, const void* src) {
    asm volatile("cp.async.ca.shared.global [%0], [%1], 16;" :: "r"(dst), "l"(src) : "memory");
}
#define CP_COMMIT() asm volatile("cp.async.commit_group;" ::: "memory")
#define CP_WAIT1()  asm volatile("cp.async.wait_group 1;" ::: "memory")
#define CP_WAIT0()  asm volatile("cp.async.wait_group 0;" ::: "memory")

__device__ __forceinline__ void mma_tf32(float* c, const uint32_t* a, uint32_t b0, uint32_t b1) {
    asm volatile("mma.sync.aligned.m16n8k8.row.col.f32.tf32.tf32.f32 "
                 "{%0,%1,%2,%3}, {%4,%5,%6,%7}, {%8,%9}, {%0,%1,%2,%3};"
                 : "+f"(c[0]), "+f"(c[1]), "+f"(c[2]), "+f"(c[3])
                 : "r"(a[0]), "r"(a[1]), "r"(a[2]), "r"(a[3]), "r"(b0), "r"(b1));
}
__device__ __forceinline__ void ldsm4(uint32_t* r, uint32_t addr) {
    asm volatile("ldmatrix.sync.aligned.m8n8.x4.shared.b16 {%0,%1,%2,%3}, [%4];"
                 : "=r"(r[0]), "=r"(r[1]), "=r"(r[2]), "=r"(r[3]) : "r"(addr));
}

// ----------------------------------------------------------------------------
// RoPE table
// ----------------------------------------------------------------------------
__global__ void build_rope_table() {
    int idx = blockIdx.x * blockDim.x + threadIdx.x;
    if (idx >= SEQ * 32) return;
    int s = idx / 32, j = idx % 32;
    double invf = exp(-(double)j * (9.210340371976184 / 32.0));
    double a = (double)s * invf;
    g_cos[idx] = (float)cos(a);
    g_sin[idx] = (float)sin(a);
}

// w1 row-permute: dst row 2j <- src j (u1), dst row 2j+1 <- src DFF+j (u2)
__global__ __launch_bounds__(256) void perm_w1(const float4* __restrict__ in,
                                               float4* __restrict__ out) {
    int i = blockIdx.x * 256 + threadIdx.x;
    const int C4 = DMODEL / 4;
    if (i >= 2 * DFF * C4) return;
    int row = i / C4, c = i % C4;
    int src = (row & 1) ? (DFF + (row >> 1)) : (row >> 1);
    out[i] = in[(size_t)src * C4 + c];
}

// ----------------------------------------------------------------------------
// RMSNorm
// ----------------------------------------------------------------------------
__global__ __launch_bounds__(256) void rmsnorm_k(const float* __restrict__ x,
                                                 const float* __restrict__ g,
                                                 float* __restrict__ o) {
    int row = blockIdx.x;
    const float* xr = x + (size_t)row * DMODEL;
    float ss = 0.f;
    for (int c = threadIdx.x; c < DMODEL; c += 256) { float v = xr[c]; ss += v * v; }
    __shared__ float sm[8];
    for (int off = 16; off; off >>= 1) ss += __shfl_down_sync(0xffffffffu, ss, off);
    if ((threadIdx.x & 31) == 0) sm[threadIdx.x >> 5] = ss;
    __syncthreads();
    if (threadIdx.x < 8) {
        float v = sm[threadIdx.x];
        for (int off = 4; off; off >>= 1) v += __shfl_down_sync(0xffu, v, off);
        if (threadIdx.x == 0) sm[0] = v;
    }
    __syncthreads();
    float inv = 1.0f / sqrtf(sm[0] / (float)DMODEL + 1e-6f);
    float* orow = o + (size_t)row * DMODEL;
    for (int c = threadIdx.x; c < DMODEL; c += 256) orow[c] = xr[c] * inv * g[c];
}

// ----------------------------------------------------------------------------
// TF32 mma.sync GEMM, BK=32, 2-stage cp.async, 2 CTAs/SM.
// C[M,N] = A[M,K] @ B[N,K]^T.  BM=128 BN=128, 256 thr, warps 4m x 2n.
// MODE 0: plain store (+res).  MODE 3: SwiGLU pairs (w1 row-permuted).
// MODE 4: fused QKV epilogue (region by n0: q/k get RoPE, v transpose only).
// ----------------------------------------------------------------------------
#define BK 32
#define LDT 36
#define STG_F (128*LDT)                 // 4608 floats
#define GSTAGES 2
#define GEMM_SMEM (GSTAGES*2*STG_F*4)   // 73728 bytes

template<int MODE>
__global__ void __launch_bounds__(256, 2) gemm_mma(
    const float* __restrict__ A, const float* __restrict__ B,
    const float* __restrict__ res, float* __restrict__ C,
    float* __restrict__ Ck, float* __restrict__ Cv,
    int M, int N, int K)
{
    extern __shared__ float smf[];
    float* As = smf;
    float* Bs = smf + GSTAGES * STG_F;
    const uint32_t asu = smem_u32(As);
    const uint32_t bsu = smem_u32(Bs);

    const int tid = threadIdx.x;
    const int wid = tid >> 5, lane = tid & 31;
    const int wm = wid & 3, wn = wid >> 2;       // warp grid 4x2
    const int g = lane >> 2, tg = lane & 3;
    const int m0 = blockIdx.y * 128, n0 = blockIdx.x * 128;

    const int r0 = tid >> 3;                     // 0..31
    const int c0 = (tid & 7) * 4;                // 0..28
    const float* Ag = A + (size_t)(m0 + r0) * K + c0;
    const float* Bg = B + (size_t)(n0 + r0) * K + c0;
    const uint32_t lda = asu + (r0 * LDT + c0) * 4;
    const uint32_t ldb = bsu + (r0 * LDT + c0) * 4;

    const int niter = K >> 5;

    // prologue: issue stage 0
#pragma unroll
    for (int it = 0; it < 4; it++) {
        cp16(lda + it * 32 * LDT * 4, Ag + (size_t)it * 32 * K);
        cp16(ldb + it * 32 * LDT * 4, Bg + (size_t)it * 32 * K);
    }
    CP_COMMIT();

    float c[2][8][4] = {};

    const int r15 = lane & 15;
    const int ch16 = (lane >> 4) << 4;
    const uint32_t aAddr0 = (uint32_t)((wm * 32 + r15) * LDT * 4 + ch16);
    const uint32_t bAddr0 = (uint32_t)((wn * 64 + r15) * LDT * 4 + ch16);

    for (int i = 0; i < niter; i++) {
        int nb = i + 1;
        if (nb < niter) {
            int s = nb & 1;
            uint32_t da = lda + s * STG_F * 4;
            uint32_t db = ldb + s * STG_F * 4;
#pragma unroll
            for (int it = 0; it < 4; it++) {
                cp16(da + it * 32 * LDT * 4, Ag + (size_t)it * 32 * K + nb * BK);
                cp16(db + it * 32 * LDT * 4, Bg + (size_t)it * 32 * K + nb * BK);
            }
        }
        CP_COMMIT();
        CP_WAIT1();
        __syncthreads();

        const uint32_t stA = asu + (i & 1) * STG_F * 4 + aAddr0;
        const uint32_t stB = bsu + (i & 1) * STG_F * 4 + bAddr0;
#pragma unroll
        for (int ks = 0; ks < 4; ks++) {
            uint32_t a0[4], a1[4], bf[4][4];
            ldsm4(a0, stA + ks * 32);
            ldsm4(a1, stA + 16 * LDT * 4 + ks * 32);
#pragma unroll
            for (int grp = 0; grp < 4; grp++)
                ldsm4(bf[grp], stB + grp * 16 * LDT * 4 + ks * 32);
#pragma unroll
            for (int ni = 0; ni < 8; ni++) {
                int grp = ni >> 1, odd = ni & 1;
                mma_tf32(c[0][ni], a0, bf[grp][odd], bf[grp][2 + odd]);
                mma_tf32(c[1][ni], a1, bf[grp][odd], bf[grp][2 + odd]);
            }
        }
        __syncthreads();
    }

    // ---------------- epilogues ----------------
    if (MODE == 0) {
#pragma unroll
        for (int mi = 0; mi < 2; mi++) {
            int r = m0 + wm * 32 + mi * 16 + g;
#pragma unroll
            for (int ni = 0; ni < 8; ni++) {
                int cc = n0 + wn * 64 + ni * 8 + tg * 2;
                size_t o1 = (size_t)r * N + cc;
                size_t o2 = (size_t)(r + 8) * N + cc;
                float2 v1 = make_float2(c[mi][ni][0], c[mi][ni][1]);
                float2 v2 = make_float2(c[mi][ni][2], c[mi][ni][3]);
                if (res) {
                    float2 r1 = *reinterpret_cast<const float2*>(res + o1);
                    float2 r2 = *reinterpret_cast<const float2*>(res + o2);
                    v1.x += r1.x; v1.y += r1.y; v2.x += r2.x; v2.y += r2.y;
                }
                *reinterpret_cast<float2*>(C + o1) = v1;
                *reinterpret_cast<float2*>(C + o2) = v2;
            }
        }
    } else if (MODE == 4) {
        int region = n0 >> 10;                  // 0=q,1=k,2=v
        int nloc = n0 & 1023;
        float* OUT = (region == 0) ? C : (region == 1) ? Ck : Cv;
        int h = (nloc + wn * 64) >> 6;
        bool doRope = (region < 2);
#pragma unroll
        for (int mi = 0; mi < 2; mi++) {
#pragma unroll
            for (int half = 0; half < 2; half++) {
                int r = m0 + wm * 32 + mi * 16 + g + half * 8;
                int bb = r >> 11, s = r & 2047;
                size_t base = (((size_t)(bb * NHEAD + h)) * SEQ + s) * 64;
                if (!doRope) {
#pragma unroll
                    for (int ni = 0; ni < 8; ni++) {
                        float2 v = make_float2(c[mi][ni][half*2], c[mi][ni][half*2+1]);
                        *reinterpret_cast<float2*>(OUT + base + ni * 8 + tg * 2) = v;
                    }
                } else {
#pragma unroll
                    for (int ni = 0; ni < 4; ni++) {
                        int dk0 = ni * 8 + tg * 2;
                        float2 o1, o2;
#pragma unroll
                        for (int j = 0; j < 2; j++) {
                            int dk = dk0 + j;
                            float x1 = c[mi][ni][half*2 + j];
                            float x2 = c[mi][ni+4][half*2 + j];
                            float cs = g_cos[s * 32 + dk];
                            float sn = g_sin[s * 32 + dk];
                            float v1 = x1 * cs - x2 * sn;
                            float v2 = x2 * cs + x1 * sn;
                            if (j == 0) { o1.x = v1; o2.x = v2; }
                            else        { o1.y = v1; o2.y = v2; }
                        }
                        *reinterpret_cast<float2*>(OUT + base + dk0)      = o1;
                        *reinterpret_cast<float2*>(OUT + base + dk0 + 32) = o2;
                    }
                }
            }
        }
    } else {  // MODE 3: SwiGLU — output width N/2
        const int NO = N >> 1;
#pragma unroll
        for (int mi = 0; mi < 2; mi++) {
            int r = m0 + wm * 32 + mi * 16 + g;
#pragma unroll
            for (int ni = 0; ni < 8; ni++) {
                int oc = (n0 + wn * 64 + ni * 8) / 2 + tg;
                float u1a = c[mi][ni][0], u2a = c[mi][ni][1];
                float u1b = c[mi][ni][2], u2b = c[mi][ni][3];
                C[(size_t)r * NO + oc]       = u1a * (u2a / (1.0f + expf(-u2a)));
                C[(size_t)(r + 8) * NO + oc] = u1b * (u2b / (1.0f + expf(-u2b)));
            }
        }
    }
}

// ----------------------------------------------------------------------------
// Flash attention on tensor cores (tf32 mma.sync), causal, 64x64 tiles.
// ----------------------------------------------------------------------------
#define FA_LDA 68
#define FA_TILE (64*FA_LDA)
#define FA_SMEM ((6*FA_TILE + 192)*4)   // 105984 bytes

__global__ void __launch_bounds__(256, 2) flash_attn_tc(
    const float* __restrict__ Q, const float* __restrict__ Kg,
    const float* __restrict__ Vg, float* __restrict__ ctx)
{
    extern __shared__ float fs[];
    float* Qs   = fs;
    float* Ks   = fs + FA_TILE;
    float* Vs   = fs + 3 * FA_TILE;
    float* Ps   = fs + 5 * FA_TILE;
    float* rowm = fs + 6 * FA_TILE;
    float* rowl = rowm + 64;
    float* rowsc = rowl + 64;

    const uint32_t qsu = smem_u32(Qs);
    const uint32_t ksu = smem_u32(Ks);
    const uint32_t vsu = smem_u32(Vs);
    const uint32_t psu = smem_u32(Ps);

    const int qt = (int)gridDim.x - 1 - (int)blockIdx.x;
    const int bh = blockIdx.y;
    const int tid = threadIdx.x;
    const int wid = tid >> 5, lane = tid & 31;
    const int wm = wid & 3, wn = wid >> 2;
    const int g = lane >> 2, tg = lane & 3;
    const int r15 = lane & 15;
    const int ch16 = (lane >> 4) << 4;

    const size_t baseQ = ((size_t)bh * SEQ + (size_t)qt * 64) * DHEAD;
#pragma unroll
    for (int it = 0; it < 4; it++) {
        int idx = tid + it * 256;
        int r = idx >> 4, c4 = (idx & 15) * 4;
        *reinterpret_cast<float4*>(Qs + r * FA_LDA + c4) =
            *reinterpret_cast<const float4*>(Q + baseQ + (size_t)r * DHEAD + c4);
    }
    if (tid < 64) { rowm[tid] = -1e30f; rowl[tid] = 0.f; }

    const int ntile = qt + 1;
    const int qbase = qt * 64;

    {
        const float* Kb = Kg + ((size_t)bh * SEQ) * DHEAD;
        const float* Vb = Vg + ((size_t)bh * SEQ) * DHEAD;
#pragma unroll
        for (int it = 0; it < 4; it++) {
            int idx = tid + it * 256;
            int r = idx >> 4, c4 = (idx & 15) * 4;
            cp16(ksu + (r * FA_LDA + c4) * 4, Kb + (size_t)r * DHEAD + c4);
            cp16(vsu + (r * FA_LDA + c4) * 4, Vb + (size_t)r * DHEAD + c4);
        }
        CP_COMMIT();
    }

    float co[4][4] = {};

    for (int kt = 0; kt < ntile; kt++) {
        const int buf = kt & 1;
        if (kt + 1 < ntile) {
            const float* Kb = Kg + ((size_t)bh * SEQ + (size_t)(kt+1) * 64) * DHEAD;
            const float* Vb = Vg + ((size_t)bh * SEQ + (size_t)(kt+1) * 64) * DHEAD;
            uint32_t kd = ksu + ((buf ^ 1) * FA_TILE) * 4;
            uint32_t vd = vsu + ((buf ^ 1) * FA_TILE) * 4;
#pragma unroll
            for (int it = 0; it < 4; it++) {
                int idx = tid + it * 256;
                int r = idx >> 4, c4 = (idx & 15) * 4;
                cp16(kd + (r * FA_LDA + c4) * 4, Kb + (size_t)r * DHEAD + c4);
                cp16(vd + (r * FA_LDA + c4) * 4, Vb + (size_t)r * DHEAD + c4);
            }
            CP_COMMIT();
            CP_WAIT1();
        } else {
            CP_WAIT0();
        }
        __syncthreads();

        // ---- S = Q @ K^T ----
        float cs_[4][4] = {};
        {
            const uint32_t aQ = qsu + ((wm * 16 + r15) * FA_LDA) * 4 + ch16;
            const uint32_t bK = ksu + (buf * FA_TILE + (wn * 32 + r15) * FA_LDA) * 4 + ch16;
#pragma unroll
            for (int ks = 0; ks < 8; ks++) {
                uint32_t qa[4], k0f[4], k1f[4];
                ldsm4(qa, aQ + ks * 32);
                ldsm4(k0f, bK + ks * 32);
                ldsm4(k1f, bK + 16 * FA_LDA * 4 + ks * 32);
                mma_tf32(cs_[0], qa, k0f[0], k0f[2]);
                mma_tf32(cs_[1], qa, k0f[1], k0f[3]);
                mma_tf32(cs_[2], qa, k1f[0], k1f[2]);
                mma_tf32(cs_[3], qa, k1f[1], k1f[3]);
            }
        }

        // ---- mask + scale -> Ps ----
        {
            const int kb = kt * 64;
#pragma unroll
            for (int ni = 0; ni < 4; ni++) {
                int cc = wn * 32 + ni * 8 + tg * 2;
#pragma unroll
                for (int half = 0; half < 2; half++) {
                    int r = wm * 16 + g + half * 8;
                    int qg = qbase + r;
                    float v0 = cs_[ni][half*2]   * 0.125f;
                    float v1 = cs_[ni][half*2+1] * 0.125f;
                    Ps[r * FA_LDA + cc]     = (kb + cc     <= qg) ? v0 : -1e9f;
                    Ps[r * FA_LDA + cc + 1] = (kb + cc + 1 <= qg) ? v1 : -1e9f;
                }
            }
        }
        __syncthreads();

        // ---- online softmax ----
        {
            int r = tid >> 2, q = tid & 3;
            float* Sr = &Ps[r * FA_LDA + q * 16];
            float mx = -1e30f;
#pragma unroll
            for (int c = 0; c < 16; c++) mx = fmaxf(mx, Sr[c]);
            mx = fmaxf(mx, __shfl_xor_sync(0xffffffffu, mx, 1));
            mx = fmaxf(mx, __shfl_xor_sync(0xffffffffu, mx, 2));
            float mOld = rowm[r];
            float mn = fmaxf(mOld, mx);
            float l = 0.f;
#pragma unroll
            for (int c = 0; c < 16; c++) {
                float e = __expf(Sr[c] - mn);
                Sr[c] = e; l += e;
            }
            l += __shfl_xor_sync(0xffffffffu, l, 1);
            l += __shfl_xor_sync(0xffffffffu, l, 2);
            if (q == 0) {
                float sc = __expf(mOld - mn);
                rowsc[r] = sc;
                rowl[r] = rowl[r] * sc + l;
                rowm[r] = mn;
            }
        }
        __syncthreads();

        // ---- rescale O, then O += P @ V ----
        {
            float scg  = rowsc[wm * 16 + g];
            float scg8 = rowsc[wm * 16 + g + 8];
#pragma unroll
            for (int ni = 0; ni < 4; ni++) {
                co[ni][0] *= scg;  co[ni][1] *= scg;
                co[ni][2] *= scg8; co[ni][3] *= scg8;
            }
            const uint32_t aP = psu + ((wm * 16 + r15) * FA_LDA) * 4 + ch16;
            const float* Vb = Vs + buf * FA_TILE;
#pragma unroll
            for (int ks = 0; ks < 8; ks++) {
                uint32_t pa[4];
                ldsm4(pa, aP + ks * 32);
                const float* vrow = Vb + (ks * 8 + tg) * FA_LDA;
#pragma unroll
                for (int ni = 0; ni < 4; ni++) {
                    int n0g = wn * 32 + ni * 8 + g;
                    uint32_t b0 = __float_as_uint(vrow[n0g]);
                    uint32_t b1 = __float_as_uint(vrow[4 * FA_LDA + n0g]);
                    mma_tf32(co[ni], pa, b0, b1);
                }
            }
        }
        __syncthreads();
    }

    // ---- final write ----
    {
        int b = bh >> 4, h = bh & 15;
        float il_g  = 1.0f / rowl[wm * 16 + g];
        float il_g8 = 1.0f / rowl[wm * 16 + g + 8];
#pragma unroll
        for (int half = 0; half < 2; half++) {
            int r = wm * 16 + g + half * 8;
            float il = half ? il_g8 : il_g;
            size_t grow = ((size_t)b * SEQ + qbase + r) * DMODEL + h * 64;
#pragma unroll
            for (int ni = 0; ni < 4; ni++) {
                int d0 = wn * 32 + ni * 8 + tg * 2;
                float2 v = make_float2(co[ni][half*2] * il, co[ni][half*2+1] * il);
                *reinterpret_cast<float2*>(ctx + grow + d0) = v;
            }
        }
    }
}

// ----------------------------------------------------------------------------
// Launch
// ----------------------------------------------------------------------------
extern "C" void kernel_launch(void* const* d_in, const int* in_sizes, int n_in,
                              void* d_out, int out_size) {
    const float* x  = (const float*)d_in[0];
    const float* wq = (const float*)d_in[2];
    const float* wk = (const float*)d_in[3];
    const float* wv = (const float*)d_in[4];
    const float* wo = (const float*)d_in[5];
    const float* w1 = (const float*)d_in[6];
    const float* w2 = (const float*)d_in[7];
    const float* g1 = (const float*)d_in[8];
    const float* g2 = (const float*)d_in[9];
    float* out = (float*)d_out;

    static float *p_h=nullptr,*p_q=nullptr,*p_k=nullptr,*p_v=nullptr,
                 *p_ctx=nullptr,*p_x2=nullptr,*p_ffn=nullptr,
                 *p_wqkv=nullptr,*p_w1p=nullptr;
    if (!p_h) {
        cudaGetSymbolAddress((void**)&p_h,    g_h);
        cudaGetSymbolAddress((void**)&p_q,    g_q);
        cudaGetSymbolAddress((void**)&p_k,    g_k);
        cudaGetSymbolAddress((void**)&p_v,    g_v);
        cudaGetSymbolAddress((void**)&p_ctx,  g_ctx);
        cudaGetSymbolAddress((void**)&p_x2,   g_x2);
        cudaGetSymbolAddress((void**)&p_ffn,  g_ffn);
        cudaGetSymbolAddress((void**)&p_wqkv, g_wqkv);
        cudaGetSymbolAddress((void**)&p_w1p,  g_w1p);
        cudaFuncSetAttribute(gemm_mma<0>, cudaFuncAttributeMaxDynamicSharedMemorySize, GEMM_SMEM);
        cudaFuncSetAttribute(gemm_mma<3>, cudaFuncAttributeMaxDynamicSharedMemorySize, GEMM_SMEM);
        cudaFuncSetAttribute(gemm_mma<4>, cudaFuncAttributeMaxDynamicSharedMemorySize, GEMM_SMEM);
        cudaFuncSetAttribute(flash_attn_tc, cudaFuncAttributeMaxDynamicSharedMemorySize, FA_SMEM);
    }

    build_rope_table<<<(SEQ * 32 + 255) / 256, 256>>>();
    perm_w1<<<(2*DFF*(DMODEL/4) + 255)/256, 256>>>((const float4*)w1, (float4*)p_w1p);

    const size_t WB = (size_t)DMODEL * DMODEL * sizeof(float);
    cudaMemcpyAsync(p_wqkv,                    wq, WB, cudaMemcpyDeviceToDevice);
    cudaMemcpyAsync(p_wqkv + (size_t)DMODEL*DMODEL,   wk, WB, cudaMemcpyDeviceToDevice);
    cudaMemcpyAsync(p_wqkv + (size_t)2*DMODEL*DMODEL, wv, WB, cudaMemcpyDeviceToDevice);

    // --- attention sublayer ---
    rmsnorm_k<<<ROWS, 256>>>(x, g1, p_h);

    dim3 gqkv(3 * DMODEL / 128, ROWS / 128);   // (24, 32)
    gemm_mma<4><<<gqkv, 256, GEMM_SMEM>>>(p_h, p_wqkv, nullptr, p_q, p_k, p_v,
                                          ROWS, 3 * DMODEL, DMODEL);

    flash_attn_tc<<<dim3(SEQ / 64, BATCH * NHEAD), 256, FA_SMEM>>>(p_q, p_k, p_v, p_ctx);

    dim3 gproj(DMODEL / 128, ROWS / 128);      // (8, 32)
    gemm_mma<0><<<gproj, 256, GEMM_SMEM>>>(p_ctx, wo, x, p_x2, nullptr, nullptr,
                                           ROWS, DMODEL, DMODEL);

    // --- FFN sublayer ---
    rmsnorm_k<<<ROWS, 256>>>(p_x2, g2, p_h);
    dim3 gup(2 * DFF / 128, ROWS / 128);       // (64, 32)
    gemm_mma<3><<<gup, 256, GEMM_SMEM>>>(p_h, p_w1p, nullptr, p_ffn, nullptr, nullptr,
                                         ROWS, 2 * DFF, DMODEL);
    dim3 gdown(DMODEL / 128, ROWS / 128);      // (8, 32)
    gemm_mma<0><<<gdown, 256, GEMM_SMEM>>>(p_ffn, w2, p_x2, out, nullptr, nullptr,
                                           ROWS, DMODEL, DFF);
}

// round 9
// speedup vs baseline: 3.5817x; 1.0057x over previous
#include <cuda_runtime.h>
#include <cuda_bf16.h>
#include <math.h>
#include <stdint.h>

// Problem constants
#define BATCH 2
#define SEQ   2048
#define DMODEL 1024
#define NHEAD 16
#define DHEAD 64
#define DFF   4096
#define ROWS  (BATCH*SEQ)   // 4096

// ----------------------------------------------------------------------------
// Scratch (device globals; no allocations allowed)
// ----------------------------------------------------------------------------
__device__ float g_h   [(size_t)ROWS*DMODEL];
__device__ float g_q   [(size_t)ROWS*DMODEL];
__device__ float g_k   [(size_t)ROWS*DMODEL];
__device__ float g_v   [(size_t)ROWS*DMODEL];
__device__ float g_ctx [(size_t)ROWS*DMODEL];
__device__ float g_x2  [(size_t)ROWS*DMODEL];
__device__ float g_ffn [(size_t)ROWS*DFF];
__device__ float g_cos [SEQ*32];
__device__ float g_sin [SEQ*32];

// ----------------------------------------------------------------------------
// Helpers
// ----------------------------------------------------------------------------
__device__ __forceinline__ uint32_t smem_u32(const void* p) {
    uint32_t a;
    asm("{ .reg .u64 t; cvta.to.shared.u64 t, %1; cvt.u32.u64 %0, t; }" : "=r"(a) : "l"(p));
    return a;
}
__device__ __forceinline__ void cp16(uint32_t dst, const void* src) {
    asm volatile("cp.async.ca.shared.global [%0], [%1], 16;" :: "r"(dst), "l"(src) : "memory");
}
#define CP_COMMIT() asm volatile("cp.async.commit_group;" ::: "memory")
#define CP_WAIT1()  asm volatile("cp.async.wait_group 1;" ::: "memory")
#define CP_WAIT0()  asm volatile("cp.async.wait_group 0;" ::: "memory")

__device__ __forceinline__ void mma_tf32(float* c, const uint32_t* a, uint32_t b0, uint32_t b1) {
    asm volatile("mma.sync.aligned.m16n8k8.row.col.f32.tf32.tf32.f32 "
                 "{%0,%1,%2,%3}, {%4,%5,%6,%7}, {%8,%9}, {%0,%1,%2,%3};"
                 : "+f"(c[0]), "+f"(c[1]), "+f"(c[2]), "+f"(c[3])
                 : "r"(a[0]), "r"(a[1]), "r"(a[2]), "r"(a[3]), "r"(b0), "r"(b1));
}
__device__ __forceinline__ void ldsm4(uint32_t* r, uint32_t addr) {
    asm volatile("ldmatrix.sync.aligned.m8n8.x4.shared.b16 {%0,%1,%2,%3}, [%4];"
                 : "=r"(r[0]), "=r"(r[1]), "=r"(r[2]), "=r"(r[3]) : "r"(addr));
}

// ----------------------------------------------------------------------------
// RoPE table
// ----------------------------------------------------------------------------
__global__ void build_rope_table() {
    int idx = blockIdx.x * blockDim.x + threadIdx.x;
    if (idx >= SEQ * 32) return;
    int s = idx / 32, j = idx % 32;
    double invf = exp(-(double)j * (9.210340371976184 / 32.0));
    double a = (double)s * invf;
    g_cos[idx] = (float)cos(a);
    g_sin[idx] = (float)sin(a);
}

// ----------------------------------------------------------------------------
// RMSNorm
// ----------------------------------------------------------------------------
__global__ __launch_bounds__(256) void rmsnorm_k(const float* __restrict__ x,
                                                 const float* __restrict__ g,
                                                 float* __restrict__ o) {
    int row = blockIdx.x;
    const float* xr = x + (size_t)row * DMODEL;
    float ss = 0.f;
    for (int c = threadIdx.x; c < DMODEL; c += 256) { float v = xr[c]; ss += v * v; }
    __shared__ float sm[8];
    for (int off = 16; off; off >>= 1) ss += __shfl_down_sync(0xffffffffu, ss, off);
    if ((threadIdx.x & 31) == 0) sm[threadIdx.x >> 5] = ss;
    __syncthreads();
    if (threadIdx.x < 8) {
        float v = sm[threadIdx.x];
        for (int off = 4; off; off >>= 1) v += __shfl_down_sync(0xffu, v, off);
        if (threadIdx.x == 0) sm[0] = v;
    }
    __syncthreads();
    float inv = 1.0f / sqrtf(sm[0] / (float)DMODEL + 1e-6f);
    float* orow = o + (size_t)row * DMODEL;
    for (int c = threadIdx.x; c < DMODEL; c += 256) orow[c] = xr[c] * inv * g[c];
}

// ----------------------------------------------------------------------------
// TF32 mma.sync GEMM. BM=128 BN=256 BK=32, 2-stage cp.async, 1 CTA/SM.
// 256 threads = 8 warps, warp grid 2m x 4n, warp tile 64x64.
// C[M,N] = A[M,K] @ B[N,K]^T.
// MODE 0: plain store (+res).
// MODE 3: SwiGLU pairs; w1 row-permutation applied at LOAD TIME (u1/u2 interleave).
// MODE 4: fused QKV; weight selected per 256-col region from B/B2/B3;
//         epilogue does RoPE (q,k) or transpose (v).
// ----------------------------------------------------------------------------
#define BK 32
#define LDT 36
#define STG_A (128*LDT)                 // 4608 floats
#define STG_B (256*LDT)                 // 9216 floats
#define STG_T (STG_A+STG_B)             // 13824 floats
#define GEMM_SMEM (2*STG_T*4)           // 110592 bytes

template<int MODE>
__global__ void __launch_bounds__(256, 1) gemm_mma(
    const float* __restrict__ A, const float* __restrict__ B,
    const float* __restrict__ B2, const float* __restrict__ B3,
    const float* __restrict__ res, float* __restrict__ C,
    float* __restrict__ Ck, float* __restrict__ Cv,
    int M, int N, int K)
{
    extern __shared__ float smf[];
    const uint32_t ssu = smem_u32(smf);

    const int tid = threadIdx.x;
    const int wid = tid >> 5, lane = tid & 31;
    const int wm = wid & 1, wn = wid >> 1;       // warp grid 2m x 4n
    const int g = lane >> 2, tg = lane & 3;
    const int m0 = blockIdx.y * 128, n0 = blockIdx.x * 256;

    const int r0 = tid >> 3;                     // 0..31
    const int c0 = (tid & 7) * 4;                // 0..28

    // per-thread global row pointers (permutation / weight-select folded here)
    const float* rowPtrA[4];
#pragma unroll
    for (int it = 0; it < 4; it++)
        rowPtrA[it] = A + (size_t)(m0 + r0 + it * 32) * K + c0;

    const float* rowPtrB[8];
    if (MODE == 4) {
        int region = n0 >> 10, nloc = n0 & 1023;
        const float* W = (region == 0) ? B : (region == 1) ? B2 : B3;
#pragma unroll
        for (int it = 0; it < 8; it++)
            rowPtrB[it] = W + (size_t)(nloc + r0 + it * 32) * K + c0;
    } else if (MODE == 3) {
#pragma unroll
        for (int it = 0; it < 8; it++) {
            int gr = n0 + r0 + it * 32;
            int src = (gr & 1) ? (DFF + (gr >> 1)) : (gr >> 1);
            rowPtrB[it] = B + (size_t)src * K + c0;
        }
    } else {
#pragma unroll
        for (int it = 0; it < 8; it++)
            rowPtrB[it] = B + (size_t)(n0 + r0 + it * 32) * K + c0;
    }

    const uint32_t stAoff = ssu + (r0 * LDT + c0) * 4;
    const uint32_t stBoff = ssu + STG_A * 4 + (r0 * LDT + c0) * 4;

    const int niter = K >> 5;

    // prologue: stage 0
#pragma unroll
    for (int it = 0; it < 4; it++)
        cp16(stAoff + it * 32 * LDT * 4, rowPtrA[it]);
#pragma unroll
    for (int it = 0; it < 8; it++)
        cp16(stBoff + it * 32 * LDT * 4, rowPtrB[it]);
    CP_COMMIT();

    float c[4][8][4] = {};

    const int r15 = lane & 15;
    const int ch16 = (lane >> 4) << 4;
    const uint32_t aAddr0 = (uint32_t)((wm * 64 + r15) * LDT * 4 + ch16);
    const uint32_t bAddr0 = (uint32_t)((wn * 64 + r15) * LDT * 4 + ch16) + STG_A * 4;

    for (int i = 0; i < niter; i++) {
        int nb = i + 1;
        if (nb < niter) {
            uint32_t off = (nb & 1) * STG_T * 4;
            int ko = nb * BK;
#pragma unroll
            for (int it = 0; it < 4; it++)
                cp16(stAoff + off + it * 32 * LDT * 4, rowPtrA[it] + ko);
#pragma unroll
            for (int it = 0; it < 8; it++)
                cp16(stBoff + off + it * 32 * LDT * 4, rowPtrB[it] + ko);
        }
        CP_COMMIT();
        CP_WAIT1();
        __syncthreads();

        const uint32_t stA = ssu + (i & 1) * STG_T * 4 + aAddr0;
        const uint32_t stB = ssu + (i & 1) * STG_T * 4 + bAddr0;
#pragma unroll
        for (int ks = 0; ks < 4; ks++) {
            uint32_t af[4][4], bf[4][4];
#pragma unroll
            for (int mi = 0; mi < 4; mi++)
                ldsm4(af[mi], stA + mi * 16 * LDT * 4 + ks * 32);
#pragma unroll
            for (int grp = 0; grp < 4; grp++)
                ldsm4(bf[grp], stB + grp * 16 * LDT * 4 + ks * 32);
#pragma unroll
            for (int mi = 0; mi < 4; mi++)
#pragma unroll
                for (int ni = 0; ni < 8; ni++) {
                    int grp = ni >> 1, odd = ni & 1;
                    mma_tf32(c[mi][ni], af[mi], bf[grp][odd], bf[grp][2 + odd]);
                }
        }
        __syncthreads();
    }

    // ---------------- epilogues ----------------
    if (MODE == 0) {
#pragma unroll
        for (int mi = 0; mi < 4; mi++) {
            int r = m0 + wm * 64 + mi * 16 + g;
#pragma unroll
            for (int ni = 0; ni < 8; ni++) {
                int cc = n0 + wn * 64 + ni * 8 + tg * 2;
                size_t o1 = (size_t)r * N + cc;
                size_t o2 = (size_t)(r + 8) * N + cc;
                float2 v1 = make_float2(c[mi][ni][0], c[mi][ni][1]);
                float2 v2 = make_float2(c[mi][ni][2], c[mi][ni][3]);
                if (res) {
                    float2 r1 = *reinterpret_cast<const float2*>(res + o1);
                    float2 r2 = *reinterpret_cast<const float2*>(res + o2);
                    v1.x += r1.x; v1.y += r1.y; v2.x += r2.x; v2.y += r2.y;
                }
                *reinterpret_cast<float2*>(C + o1) = v1;
                *reinterpret_cast<float2*>(C + o2) = v2;
            }
        }
    } else if (MODE == 4) {
        int region = n0 >> 10, nloc = n0 & 1023;
        float* OUT = (region == 0) ? C : (region == 1) ? Ck : Cv;
        int h = (nloc + wn * 64) >> 6;           // one head per warp column
        bool doRope = (region < 2);
#pragma unroll
        for (int mi = 0; mi < 4; mi++) {
#pragma unroll
            for (int half = 0; half < 2; half++) {
                int r = m0 + wm * 64 + mi * 16 + g + half * 8;
                int bb = r >> 11, s = r & 2047;
                size_t base = (((size_t)(bb * NHEAD + h)) * SEQ + s) * 64;
                if (!doRope) {
#pragma unroll
                    for (int ni = 0; ni < 8; ni++) {
                        float2 v = make_float2(c[mi][ni][half*2], c[mi][ni][half*2+1]);
                        *reinterpret_cast<float2*>(OUT + base + ni * 8 + tg * 2) = v;
                    }
                } else {
#pragma unroll
                    for (int ni = 0; ni < 4; ni++) {
                        int dk0 = ni * 8 + tg * 2;
                        float2 o1, o2;
#pragma unroll
                        for (int j = 0; j < 2; j++) {
                            int dk = dk0 + j;
                            float x1 = c[mi][ni][half*2 + j];
                            float x2 = c[mi][ni+4][half*2 + j];
                            float cs = g_cos[s * 32 + dk];
                            float sn = g_sin[s * 32 + dk];
                            float v1 = x1 * cs - x2 * sn;
                            float v2 = x2 * cs + x1 * sn;
                            if (j == 0) { o1.x = v1; o2.x = v2; }
                            else        { o1.y = v1; o2.y = v2; }
                        }
                        *reinterpret_cast<float2*>(OUT + base + dk0)      = o1;
                        *reinterpret_cast<float2*>(OUT + base + dk0 + 32) = o2;
                    }
                }
            }
        }
    } else {  // MODE 3: SwiGLU — output width N/2
        const int NO = N >> 1;
#pragma unroll
        for (int mi = 0; mi < 4; mi++) {
            int r = m0 + wm * 64 + mi * 16 + g;
#pragma unroll
            for (int ni = 0; ni < 8; ni++) {
                int oc = (n0 + wn * 64 + ni * 8) / 2 + tg;
                float u1a = c[mi][ni][0], u2a = c[mi][ni][1];
                float u1b = c[mi][ni][2], u2b = c[mi][ni][3];
                C[(size_t)r * NO + oc]       = u1a * (u2a / (1.0f + expf(-u2a)));
                C[(size_t)(r + 8) * NO + oc] = u1b * (u2b / (1.0f + expf(-u2b)));
            }
        }
    }
}

// ----------------------------------------------------------------------------
// Flash attention on tensor cores (tf32 mma.sync), causal, 64x64 tiles.
// ----------------------------------------------------------------------------
#define FA_LDA 68
#define FA_TILE (64*FA_LDA)
#define FA_SMEM ((6*FA_TILE + 192)*4)   // 105984 bytes

__global__ void __launch_bounds__(256, 2) flash_attn_tc(
    const float* __restrict__ Q, const float* __restrict__ Kg,
    const float* __restrict__ Vg, float* __restrict__ ctx)
{
    extern __shared__ float fs[];
    float* Qs   = fs;
    float* Ks   = fs + FA_TILE;
    float* Vs   = fs + 3 * FA_TILE;
    float* Ps   = fs + 5 * FA_TILE;
    float* rowm = fs + 6 * FA_TILE;
    float* rowl = rowm + 64;
    float* rowsc = rowl + 64;

    const uint32_t qsu = smem_u32(Qs);
    const uint32_t ksu = smem_u32(Ks);
    const uint32_t vsu = smem_u32(Vs);
    const uint32_t psu = smem_u32(Ps);

    const int qt = (int)gridDim.x - 1 - (int)blockIdx.x;
    const int bh = blockIdx.y;
    const int tid = threadIdx.x;
    const int wid = tid >> 5, lane = tid & 31;
    const int wm = wid & 3, wn = wid >> 2;
    const int g = lane >> 2, tg = lane & 3;
    const int r15 = lane & 15;
    const int ch16 = (lane >> 4) << 4;

    const size_t baseQ = ((size_t)bh * SEQ + (size_t)qt * 64) * DHEAD;
#pragma unroll
    for (int it = 0; it < 4; it++) {
        int idx = tid + it * 256;
        int r = idx >> 4, c4 = (idx & 15) * 4;
        *reinterpret_cast<float4*>(Qs + r * FA_LDA + c4) =
            *reinterpret_cast<const float4*>(Q + baseQ + (size_t)r * DHEAD + c4);
    }
    if (tid < 64) { rowm[tid] = -1e30f; rowl[tid] = 0.f; }

    const int ntile = qt + 1;
    const int qbase = qt * 64;

    {
        const float* Kb = Kg + ((size_t)bh * SEQ) * DHEAD;
        const float* Vb = Vg + ((size_t)bh * SEQ) * DHEAD;
#pragma unroll
        for (int it = 0; it < 4; it++) {
            int idx = tid + it * 256;
            int r = idx >> 4, c4 = (idx & 15) * 4;
            cp16(ksu + (r * FA_LDA + c4) * 4, Kb + (size_t)r * DHEAD + c4);
            cp16(vsu + (r * FA_LDA + c4) * 4, Vb + (size_t)r * DHEAD + c4);
        }
        CP_COMMIT();
    }

    float co[4][4] = {};

    for (int kt = 0; kt < ntile; kt++) {
        const int buf = kt & 1;
        if (kt + 1 < ntile) {
            const float* Kb = Kg + ((size_t)bh * SEQ + (size_t)(kt+1) * 64) * DHEAD;
            const float* Vb = Vg + ((size_t)bh * SEQ + (size_t)(kt+1) * 64) * DHEAD;
            uint32_t kd = ksu + ((buf ^ 1) * FA_TILE) * 4;
            uint32_t vd = vsu + ((buf ^ 1) * FA_TILE) * 4;
#pragma unroll
            for (int it = 0; it < 4; it++) {
                int idx = tid + it * 256;
                int r = idx >> 4, c4 = (idx & 15) * 4;
                cp16(kd + (r * FA_LDA + c4) * 4, Kb + (size_t)r * DHEAD + c4);
                cp16(vd + (r * FA_LDA + c4) * 4, Vb + (size_t)r * DHEAD + c4);
            }
            CP_COMMIT();
            CP_WAIT1();
        } else {
            CP_WAIT0();
        }
        __syncthreads();

        // ---- S = Q @ K^T ----
        float cs_[4][4] = {};
        {
            const uint32_t aQ = qsu + ((wm * 16 + r15) * FA_LDA) * 4 + ch16;
            const uint32_t bK = ksu + (buf * FA_TILE + (wn * 32 + r15) * FA_LDA) * 4 + ch16;
#pragma unroll
            for (int ks = 0; ks < 8; ks++) {
                uint32_t qa[4], k0f[4], k1f[4];
                ldsm4(qa, aQ + ks * 32);
                ldsm4(k0f, bK + ks * 32);
                ldsm4(k1f, bK + 16 * FA_LDA * 4 + ks * 32);
                mma_tf32(cs_[0], qa, k0f[0], k0f[2]);
                mma_tf32(cs_[1], qa, k0f[1], k0f[3]);
                mma_tf32(cs_[2], qa, k1f[0], k1f[2]);
                mma_tf32(cs_[3], qa, k1f[1], k1f[3]);
            }
        }

        // ---- mask + scale -> Ps ----
        {
            const int kb = kt * 64;
#pragma unroll
            for (int ni = 0; ni < 4; ni++) {
                int cc = wn * 32 + ni * 8 + tg * 2;
#pragma unroll
                for (int half = 0; half < 2; half++) {
                    int r = wm * 16 + g + half * 8;
                    int qg = qbase + r;
                    float v0 = cs_[ni][half*2]   * 0.125f;
                    float v1 = cs_[ni][half*2+1] * 0.125f;
                    Ps[r * FA_LDA + cc]     = (kb + cc     <= qg) ? v0 : -1e9f;
                    Ps[r * FA_LDA + cc + 1] = (kb + cc + 1 <= qg) ? v1 : -1e9f;
                }
            }
        }
        __syncthreads();

        // ---- online softmax ----
        {
            int r = tid >> 2, q = tid & 3;
            float* Sr = &Ps[r * FA_LDA + q * 16];
            float mx = -1e30f;
#pragma unroll
            for (int c = 0; c < 16; c++) mx = fmaxf(mx, Sr[c]);
            mx = fmaxf(mx, __shfl_xor_sync(0xffffffffu, mx, 1));
            mx = fmaxf(mx, __shfl_xor_sync(0xffffffffu, mx, 2));
            float mOld = rowm[r];
            float mn = fmaxf(mOld, mx);
            float l = 0.f;
#pragma unroll
            for (int c = 0; c < 16; c++) {
                float e = __expf(Sr[c] - mn);
                Sr[c] = e; l += e;
            }
            l += __shfl_xor_sync(0xffffffffu, l, 1);
            l += __shfl_xor_sync(0xffffffffu, l, 2);
            if (q == 0) {
                float sc = __expf(mOld - mn);
                rowsc[r] = sc;
                rowl[r] = rowl[r] * sc + l;
                rowm[r] = mn;
            }
        }
        __syncthreads();

        // ---- rescale O, then O += P @ V ----
        {
            float scg  = rowsc[wm * 16 + g];
            float scg8 = rowsc[wm * 16 + g + 8];
#pragma unroll
            for (int ni = 0; ni < 4; ni++) {
                co[ni][0] *= scg;  co[ni][1] *= scg;
                co[ni][2] *= scg8; co[ni][3] *= scg8;
            }
            const uint32_t aP = psu + ((wm * 16 + r15) * FA_LDA) * 4 + ch16;
            const float* Vb = Vs + buf * FA_TILE;
#pragma unroll
            for (int ks = 0; ks < 8; ks++) {
                uint32_t pa[4];
                ldsm4(pa, aP + ks * 32);
                const float* vrow = Vb + (ks * 8 + tg) * FA_LDA;
#pragma unroll
                for (int ni = 0; ni < 4; ni++) {
                    int n0g = wn * 32 + ni * 8 + g;
                    uint32_t b0 = __float_as_uint(vrow[n0g]);
                    uint32_t b1 = __float_as_uint(vrow[4 * FA_LDA + n0g]);
                    mma_tf32(co[ni], pa, b0, b1);
                }
            }
        }
        __syncthreads();
    }

    // ---- final write ----
    {
        int b = bh >> 4, h = bh & 15;
        float il_g  = 1.0f / rowl[wm * 16 + g];
        float il_g8 = 1.0f / rowl[wm * 16 + g + 8];
#pragma unroll
        for (int half = 0; half < 2; half++) {
            int r = wm * 16 + g + half * 8;
            float il = half ? il_g8 : il_g;
            size_t grow = ((size_t)b * SEQ + qbase + r) * DMODEL + h * 64;
#pragma unroll
            for (int ni = 0; ni < 4; ni++) {
                int d0 = wn * 32 + ni * 8 + tg * 2;
                float2 v = make_float2(co[ni][half*2] * il, co[ni][half*2+1] * il);
                *reinterpret_cast<float2*>(ctx + grow + d0) = v;
            }
        }
    }
}

// ----------------------------------------------------------------------------
// Launch
// ----------------------------------------------------------------------------
extern "C" void kernel_launch(void* const* d_in, const int* in_sizes, int n_in,
                              void* d_out, int out_size) {
    const float* x  = (const float*)d_in[0];
    const float* wq = (const float*)d_in[2];
    const float* wk = (const float*)d_in[3];
    const float* wv = (const float*)d_in[4];
    const float* wo = (const float*)d_in[5];
    const float* w1 = (const float*)d_in[6];
    const float* w2 = (const float*)d_in[7];
    const float* g1 = (const float*)d_in[8];
    const float* g2 = (const float*)d_in[9];
    float* out = (float*)d_out;

    static float *p_h=nullptr,*p_q=nullptr,*p_k=nullptr,*p_v=nullptr,
                 *p_ctx=nullptr,*p_x2=nullptr,*p_ffn=nullptr;
    if (!p_h) {
        cudaGetSymbolAddress((void**)&p_h,    g_h);
        cudaGetSymbolAddress((void**)&p_q,    g_q);
        cudaGetSymbolAddress((void**)&p_k,    g_k);
        cudaGetSymbolAddress((void**)&p_v,    g_v);
        cudaGetSymbolAddress((void**)&p_ctx,  g_ctx);
        cudaGetSymbolAddress((void**)&p_x2,   g_x2);
        cudaGetSymbolAddress((void**)&p_ffn,  g_ffn);
        cudaFuncSetAttribute(gemm_mma<0>, cudaFuncAttributeMaxDynamicSharedMemorySize, GEMM_SMEM);
        cudaFuncSetAttribute(gemm_mma<3>, cudaFuncAttributeMaxDynamicSharedMemorySize, GEMM_SMEM);
        cudaFuncSetAttribute(gemm_mma<4>, cudaFuncAttributeMaxDynamicSharedMemorySize, GEMM_SMEM);
        cudaFuncSetAttribute(flash_attn_tc, cudaFuncAttributeMaxDynamicSharedMemorySize, FA_SMEM);
    }

    build_rope_table<<<(SEQ * 32 + 255) / 256, 256>>>();

    // --- attention sublayer ---
    rmsnorm_k<<<ROWS, 256>>>(x, g1, p_h);

    dim3 gqkv(3 * DMODEL / 256, ROWS / 128);   // (12, 32)
    gemm_mma<4><<<gqkv, 256, GEMM_SMEM>>>(p_h, wq, wk, wv, nullptr,
                                          p_q, p_k, p_v, ROWS, 3 * DMODEL, DMODEL);

    flash_attn_tc<<<dim3(SEQ / 64, BATCH * NHEAD), 256, FA_SMEM>>>(p_q, p_k, p_v, p_ctx);

    dim3 gproj(DMODEL / 256, ROWS / 128);      // (4, 32)
    gemm_mma<0><<<gproj, 256, GEMM_SMEM>>>(p_ctx, wo, nullptr, nullptr, x,
                                           p_x2, nullptr, nullptr, ROWS, DMODEL, DMODEL);

    // --- FFN sublayer ---
    rmsnorm_k<<<ROWS, 256>>>(p_x2, g2, p_h);
    dim3 gup(2 * DFF / 256, ROWS / 128);       // (32, 32)
    gemm_mma<3><<<gup, 256, GEMM_SMEM>>>(p_h, w1, nullptr, nullptr, nullptr,
                                         p_ffn, nullptr, nullptr, ROWS, 2 * DFF, DMODEL);
    dim3 gdown(DMODEL / 256, ROWS / 128);      // (4, 32)
    gemm_mma<0><<<gdown, 256, GEMM_SMEM>>>(p_ffn, w2, nullptr, nullptr, p_x2,
                                           out, nullptr, nullptr, ROWS, DMODEL, DFF);
}

// round 10
// speedup vs baseline: 3.7884x; 1.0577x over previous
#include <cuda_runtime.h>
#include <cuda_bf16.h>
#include <math.h>
#include <stdint.h>

// Problem constants
#define BATCH 2
#define SEQ   2048
#define DMODEL 1024
#define NHEAD 16
#define DHEAD 64
#define DFF   4096
#define ROWS  (BATCH*SEQ)   // 4096

// ----------------------------------------------------------------------------
// Scratch (device globals; no allocations allowed)
// ----------------------------------------------------------------------------
__device__ float g_h   [(size_t)ROWS*DMODEL];
__device__ float g_q   [(size_t)ROWS*DMODEL];
__device__ float g_k   [(size_t)ROWS*DMODEL];
__device__ float g_v   [(size_t)ROWS*DMODEL];
__device__ float g_ctx [(size_t)ROWS*DMODEL];
__device__ float g_x2  [(size_t)ROWS*DMODEL];
__device__ float g_ffn [(size_t)ROWS*DFF];
__device__ float g_cos [SEQ*32];
__device__ float g_sin [SEQ*32];

// ----------------------------------------------------------------------------
// Helpers
// ----------------------------------------------------------------------------
__device__ __forceinline__ uint32_t smem_u32(const void* p) {
    uint32_t a;
    asm("{ .reg .u64 t; cvta.to.shared.u64 t, %1; cvt.u32.u64 %0, t; }" : "=r"(a) : "l"(p));
    return a;
}
__device__ __forceinline__ void cp16(uint32_t dst, const void* src) {
    asm volatile("cp.async.ca.shared.global [%0], [%1], 16;" :: "r"(dst), "l"(src) : "memory");
}
#define CP_COMMIT() asm volatile("cp.async.commit_group;" ::: "memory")
#define CP_WAIT1()  asm volatile("cp.async.wait_group 1;" ::: "memory")
#define CP_WAIT0()  asm volatile("cp.async.wait_group 0;" ::: "memory")

__device__ __forceinline__ void mma_tf32(float* c, const uint32_t* a, uint32_t b0, uint32_t b1) {
    asm volatile("mma.sync.aligned.m16n8k8.row.col.f32.tf32.tf32.f32 "
                 "{%0,%1,%2,%3}, {%4,%5,%6,%7}, {%8,%9}, {%0,%1,%2,%3};"
                 : "+f"(c[0]), "+f"(c[1]), "+f"(c[2]), "+f"(c[3])
                 : "r"(a[0]), "r"(a[1]), "r"(a[2]), "r"(a[3]), "r"(b0), "r"(b1));
}
__device__ __forceinline__ void ldsm4(uint32_t* r, uint32_t addr) {
    asm volatile("ldmatrix.sync.aligned.m8n8.x4.shared.b16 {%0,%1,%2,%3}, [%4];"
                 : "=r"(r[0]), "=r"(r[1]), "=r"(r[2]), "=r"(r[3]) : "r"(addr));
}

// ----------------------------------------------------------------------------
// RoPE table
// ----------------------------------------------------------------------------
__global__ void build_rope_table() {
    int idx = blockIdx.x * blockDim.x + threadIdx.x;
    if (idx >= SEQ * 32) return;
    int s = idx / 32, j = idx % 32;
    double invf = exp(-(double)j * (9.210340371976184 / 32.0));
    double a = (double)s * invf;
    g_cos[idx] = (float)cos(a);
    g_sin[idx] = (float)sin(a);
}

// ----------------------------------------------------------------------------
// RMSNorm
// ----------------------------------------------------------------------------
__global__ __launch_bounds__(256) void rmsnorm_k(const float* __restrict__ x,
                                                 const float* __restrict__ g,
                                                 float* __restrict__ o) {
    int row = blockIdx.x;
    const float* xr = x + (size_t)row * DMODEL;
    float ss = 0.f;
    for (int c = threadIdx.x; c < DMODEL; c += 256) { float v = xr[c]; ss += v * v; }
    __shared__ float sm[8];
    for (int off = 16; off; off >>= 1) ss += __shfl_down_sync(0xffffffffu, ss, off);
    if ((threadIdx.x & 31) == 0) sm[threadIdx.x >> 5] = ss;
    __syncthreads();
    if (threadIdx.x < 8) {
        float v = sm[threadIdx.x];
        for (int off = 4; off; off >>= 1) v += __shfl_down_sync(0xffu, v, off);
        if (threadIdx.x == 0) sm[0] = v;
    }
    __syncthreads();
    float inv = 1.0f / sqrtf(sm[0] / (float)DMODEL + 1e-6f);
    float* orow = o + (size_t)row * DMODEL;
    for (int c = threadIdx.x; c < DMODEL; c += 256) orow[c] = xr[c] * inv * g[c];
}

// ----------------------------------------------------------------------------
// TF32 mma.sync GEMM. BM=128 BN=256 BK=32, 2-stage cp.async, 1 CTA/SM.
// 256 threads = 8 warps, warp grid 2m x 4n, warp tile 64x64.
// MODE 0: plain store (+res).  MODE 3: SwiGLU (w1 permutation at load).
// MODE 4: fused QKV (per-region weight select; RoPE / transpose epilogue).
// ----------------------------------------------------------------------------
#define BK 32
#define LDT 36
#define STG_A (128*LDT)
#define STG_B (256*LDT)
#define STG_T (STG_A+STG_B)
#define GEMM_SMEM (2*STG_T*4)           // 110592 bytes

template<int MODE>
__global__ void __launch_bounds__(256, 1) gemm_mma(
    const float* __restrict__ A, const float* __restrict__ B,
    const float* __restrict__ B2, const float* __restrict__ B3,
    const float* __restrict__ res, float* __restrict__ C,
    float* __restrict__ Ck, float* __restrict__ Cv,
    int M, int N, int K)
{
    extern __shared__ float smf[];
    const uint32_t ssu = smem_u32(smf);

    const int tid = threadIdx.x;
    const int wid = tid >> 5, lane = tid & 31;
    const int wm = wid & 1, wn = wid >> 1;
    const int g = lane >> 2, tg = lane & 3;
    const int m0 = blockIdx.y * 128, n0 = blockIdx.x * 256;

    const int r0 = tid >> 3;
    const int c0 = (tid & 7) * 4;

    const float* rowPtrA[4];
#pragma unroll
    for (int it = 0; it < 4; it++)
        rowPtrA[it] = A + (size_t)(m0 + r0 + it * 32) * K + c0;

    const float* rowPtrB[8];
    if (MODE == 4) {
        int region = n0 >> 10, nloc = n0 & 1023;
        const float* W = (region == 0) ? B : (region == 1) ? B2 : B3;
#pragma unroll
        for (int it = 0; it < 8; it++)
            rowPtrB[it] = W + (size_t)(nloc + r0 + it * 32) * K + c0;
    } else if (MODE == 3) {
#pragma unroll
        for (int it = 0; it < 8; it++) {
            int gr = n0 + r0 + it * 32;
            int src = (gr & 1) ? (DFF + (gr >> 1)) : (gr >> 1);
            rowPtrB[it] = B + (size_t)src * K + c0;
        }
    } else {
#pragma unroll
        for (int it = 0; it < 8; it++)
            rowPtrB[it] = B + (size_t)(n0 + r0 + it * 32) * K + c0;
    }

    const uint32_t stAoff = ssu + (r0 * LDT + c0) * 4;
    const uint32_t stBoff = ssu + STG_A * 4 + (r0 * LDT + c0) * 4;

    const int niter = K >> 5;

#pragma unroll
    for (int it = 0; it < 4; it++)
        cp16(stAoff + it * 32 * LDT * 4, rowPtrA[it]);
#pragma unroll
    for (int it = 0; it < 8; it++)
        cp16(stBoff + it * 32 * LDT * 4, rowPtrB[it]);
    CP_COMMIT();

    float c[4][8][4] = {};

    const int r15 = lane & 15;
    const int ch16 = (lane >> 4) << 4;
    const uint32_t aAddr0 = (uint32_t)((wm * 64 + r15) * LDT * 4 + ch16);
    const uint32_t bAddr0 = (uint32_t)((wn * 64 + r15) * LDT * 4 + ch16) + STG_A * 4;

    for (int i = 0; i < niter; i++) {
        int nb = i + 1;
        if (nb < niter) {
            uint32_t off = (nb & 1) * STG_T * 4;
            int ko = nb * BK;
#pragma unroll
            for (int it = 0; it < 4; it++)
                cp16(stAoff + off + it * 32 * LDT * 4, rowPtrA[it] + ko);
#pragma unroll
            for (int it = 0; it < 8; it++)
                cp16(stBoff + off + it * 32 * LDT * 4, rowPtrB[it] + ko);
        }
        CP_COMMIT();
        CP_WAIT1();
        __syncthreads();

        const uint32_t stA = ssu + (i & 1) * STG_T * 4 + aAddr0;
        const uint32_t stB = ssu + (i & 1) * STG_T * 4 + bAddr0;
#pragma unroll
        for (int ks = 0; ks < 4; ks++) {
            uint32_t af[4][4], bf[4][4];
#pragma unroll
            for (int mi = 0; mi < 4; mi++)
                ldsm4(af[mi], stA + mi * 16 * LDT * 4 + ks * 32);
#pragma unroll
            for (int grp = 0; grp < 4; grp++)
                ldsm4(bf[grp], stB + grp * 16 * LDT * 4 + ks * 32);
#pragma unroll
            for (int mi = 0; mi < 4; mi++)
#pragma unroll
                for (int ni = 0; ni < 8; ni++) {
                    int grp = ni >> 1, odd = ni & 1;
                    mma_tf32(c[mi][ni], af[mi], bf[grp][odd], bf[grp][2 + odd]);
                }
        }
        __syncthreads();
    }

    if (MODE == 0) {
#pragma unroll
        for (int mi = 0; mi < 4; mi++) {
            int r = m0 + wm * 64 + mi * 16 + g;
#pragma unroll
            for (int ni = 0; ni < 8; ni++) {
                int cc = n0 + wn * 64 + ni * 8 + tg * 2;
                size_t o1 = (size_t)r * N + cc;
                size_t o2 = (size_t)(r + 8) * N + cc;
                float2 v1 = make_float2(c[mi][ni][0], c[mi][ni][1]);
                float2 v2 = make_float2(c[mi][ni][2], c[mi][ni][3]);
                if (res) {
                    float2 r1 = *reinterpret_cast<const float2*>(res + o1);
                    float2 r2 = *reinterpret_cast<const float2*>(res + o2);
                    v1.x += r1.x; v1.y += r1.y; v2.x += r2.x; v2.y += r2.y;
                }
                *reinterpret_cast<float2*>(C + o1) = v1;
                *reinterpret_cast<float2*>(C + o2) = v2;
            }
        }
    } else if (MODE == 4) {
        int region = n0 >> 10, nloc = n0 & 1023;
        float* OUT = (region == 0) ? C : (region == 1) ? Ck : Cv;
        int h = (nloc + wn * 64) >> 6;
        bool doRope = (region < 2);
#pragma unroll
        for (int mi = 0; mi < 4; mi++) {
#pragma unroll
            for (int half = 0; half < 2; half++) {
                int r = m0 + wm * 64 + mi * 16 + g + half * 8;
                int bb = r >> 11, s = r & 2047;
                size_t base = (((size_t)(bb * NHEAD + h)) * SEQ + s) * 64;
                if (!doRope) {
#pragma unroll
                    for (int ni = 0; ni < 8; ni++) {
                        float2 v = make_float2(c[mi][ni][half*2], c[mi][ni][half*2+1]);
                        *reinterpret_cast<float2*>(OUT + base + ni * 8 + tg * 2) = v;
                    }
                } else {
#pragma unroll
                    for (int ni = 0; ni < 4; ni++) {
                        int dk0 = ni * 8 + tg * 2;
                        float2 o1, o2;
#pragma unroll
                        for (int j = 0; j < 2; j++) {
                            int dk = dk0 + j;
                            float x1 = c[mi][ni][half*2 + j];
                            float x2 = c[mi][ni+4][half*2 + j];
                            float cs = g_cos[s * 32 + dk];
                            float sn = g_sin[s * 32 + dk];
                            float v1 = x1 * cs - x2 * sn;
                            float v2 = x2 * cs + x1 * sn;
                            if (j == 0) { o1.x = v1; o2.x = v2; }
                            else        { o1.y = v1; o2.y = v2; }
                        }
                        *reinterpret_cast<float2*>(OUT + base + dk0)      = o1;
                        *reinterpret_cast<float2*>(OUT + base + dk0 + 32) = o2;
                    }
                }
            }
        }
    } else {  // MODE 3
        const int NO = N >> 1;
#pragma unroll
        for (int mi = 0; mi < 4; mi++) {
            int r = m0 + wm * 64 + mi * 16 + g;
#pragma unroll
            for (int ni = 0; ni < 8; ni++) {
                int oc = (n0 + wn * 64 + ni * 8) / 2 + tg;
                float u1a = c[mi][ni][0], u2a = c[mi][ni][1];
                float u1b = c[mi][ni][2], u2b = c[mi][ni][3];
                C[(size_t)r * NO + oc]       = u1a * (u2a / (1.0f + expf(-u2a)));
                C[(size_t)(r + 8) * NO + oc] = u1b * (u2b / (1.0f + expf(-u2b)));
            }
        }
    }
}

// ----------------------------------------------------------------------------
// Flash attention (tf32 mma.sync), causal, 64x64 tiles, REGISTER softmax.
// 256 threads, warps 4m x 2n. K tiles LDA=68, V tiles LDA=72 (conflict-free).
// smem floats: Q 4352 | K 2x4352 | V 2x4608 | P 4352 | stats 384  = 27008
// ----------------------------------------------------------------------------
#define LDQ 68
#define LDV 72
#define QTI (64*LDQ)      // 4352
#define VTI (64*LDV)      // 4608
#define FA_SMEM (27008*4) // 108032 bytes

__global__ void __launch_bounds__(256, 2) flash_attn_tc(
    const float* __restrict__ Q, const float* __restrict__ Kg,
    const float* __restrict__ Vg, float* __restrict__ ctx)
{
    extern __shared__ float fs[];
    float* Qs    = fs;                  // 64x68
    float* Ks    = fs + QTI;            // 2 x 64x68
    float* Vs    = fs + 3*QTI;          // 2 x 64x72
    float* Ps    = fs + 3*QTI + 2*VTI;  // 64x68
    float* rowm  = fs + 4*QTI + 2*VTI;
    float* rowl  = rowm + 64;
    float* mpart = rowl + 64;           // [2][64]
    float* lpart = mpart + 128;         // [2][64]

    const uint32_t qsu = smem_u32(Qs);
    const uint32_t ksu = smem_u32(Ks);
    const uint32_t vsu = smem_u32(Vs);
    const uint32_t psu = smem_u32(Ps);

    const int qt = (int)gridDim.x - 1 - (int)blockIdx.x;
    const int bh = blockIdx.y;
    const int tid = threadIdx.x;
    const int wid = tid >> 5, lane = tid & 31;
    const int wm = wid & 3, wn = wid >> 2;
    const int g = lane >> 2, tg = lane & 3;
    const int r15 = lane & 15;
    const int ch16 = (lane >> 4) << 4;

    const int rA = wm * 16 + g, rB = rA + 8;

    const size_t baseQ = ((size_t)bh * SEQ + (size_t)qt * 64) * DHEAD;
#pragma unroll
    for (int it = 0; it < 4; it++) {
        int idx = tid + it * 256;
        int r = idx >> 4, c4 = (idx & 15) * 4;
        *reinterpret_cast<float4*>(Qs + r * LDQ + c4) =
            *reinterpret_cast<const float4*>(Q + baseQ + (size_t)r * DHEAD + c4);
    }
    if (tid < 64) { rowm[tid] = -1e30f; rowl[tid] = 0.f; }

    const int ntile = qt + 1;
    const int qbase = qt * 64;

    {
        const float* Kb = Kg + ((size_t)bh * SEQ) * DHEAD;
        const float* Vb = Vg + ((size_t)bh * SEQ) * DHEAD;
#pragma unroll
        for (int it = 0; it < 4; it++) {
            int idx = tid + it * 256;
            int r = idx >> 4, c4 = (idx & 15) * 4;
            cp16(ksu + (r * LDQ + c4) * 4, Kb + (size_t)r * DHEAD + c4);
            cp16(vsu + (r * LDV + c4) * 4, Vb + (size_t)r * DHEAD + c4);
        }
        CP_COMMIT();
    }

    float co[4][4] = {};

    for (int kt = 0; kt < ntile; kt++) {
        const int buf = kt & 1;
        if (kt + 1 < ntile) {
            const float* Kb = Kg + ((size_t)bh * SEQ + (size_t)(kt+1) * 64) * DHEAD;
            const float* Vb = Vg + ((size_t)bh * SEQ + (size_t)(kt+1) * 64) * DHEAD;
            uint32_t kd = ksu + ((buf ^ 1) * QTI) * 4;
            uint32_t vd = vsu + ((buf ^ 1) * VTI) * 4;
#pragma unroll
            for (int it = 0; it < 4; it++) {
                int idx = tid + it * 256;
                int r = idx >> 4, c4 = (idx & 15) * 4;
                cp16(kd + (r * LDQ + c4) * 4, Kb + (size_t)r * DHEAD + c4);
                cp16(vd + (r * LDV + c4) * 4, Vb + (size_t)r * DHEAD + c4);
            }
            CP_COMMIT();
            CP_WAIT1();
        } else {
            CP_WAIT0();
        }
        __syncthreads();

        // ---- S = Q @ K^T (fragments in cs_) ----
        float cs_[4][4] = {};
        {
            const uint32_t aQ = qsu + ((wm * 16 + r15) * LDQ) * 4 + ch16;
            const uint32_t bK = ksu + (buf * QTI + (wn * 32 + r15) * LDQ) * 4 + ch16;
#pragma unroll
            for (int ks = 0; ks < 8; ks++) {
                uint32_t qa[4], k0f[4], k1f[4];
                ldsm4(qa, aQ + ks * 32);
                ldsm4(k0f, bK + ks * 32);
                ldsm4(k1f, bK + 16 * LDQ * 4 + ks * 32);
                mma_tf32(cs_[0], qa, k0f[0], k0f[2]);
                mma_tf32(cs_[1], qa, k0f[1], k0f[3]);
                mma_tf32(cs_[2], qa, k1f[0], k1f[2]);
                mma_tf32(cs_[3], qa, k1f[1], k1f[3]);
            }
        }

        // ---- scale + causal mask in registers (diagonal tile only) ----
#pragma unroll
        for (int ni = 0; ni < 4; ni++)
#pragma unroll
            for (int jj = 0; jj < 4; jj++) cs_[ni][jj] *= 0.125f;
        if (kt == qt) {
#pragma unroll
            for (int ni = 0; ni < 4; ni++) {
                int cloc0 = wn * 32 + ni * 8 + 2 * tg;
                if (cloc0     > rA) cs_[ni][0] = -1e30f;
                if (cloc0 + 1 > rA) cs_[ni][1] = -1e30f;
                if (cloc0     > rB) cs_[ni][2] = -1e30f;
                if (cloc0 + 1 > rB) cs_[ni][3] = -1e30f;
            }
        }

        // ---- warp-level row max + cross-warp exchange ----
        {
            float mA = -1e30f, mB = -1e30f;
#pragma unroll
            for (int ni = 0; ni < 4; ni++) {
                mA = fmaxf(mA, fmaxf(cs_[ni][0], cs_[ni][1]));
                mB = fmaxf(mB, fmaxf(cs_[ni][2], cs_[ni][3]));
            }
            mA = fmaxf(mA, __shfl_xor_sync(0xffffffffu, mA, 1));
            mA = fmaxf(mA, __shfl_xor_sync(0xffffffffu, mA, 2));
            mB = fmaxf(mB, __shfl_xor_sync(0xffffffffu, mB, 1));
            mB = fmaxf(mB, __shfl_xor_sync(0xffffffffu, mB, 2));
            if (tg == 0) { mpart[wn * 64 + rA] = mA; mpart[wn * 64 + rB] = mB; }
        }
        __syncthreads();

        // ---- exp in registers, single P write, row-sum, local rescale ----
        float mnA, mnB, scA, scB;
        {
            float moA = rowm[rA], moB = rowm[rB];
            mnA = fmaxf(moA, fmaxf(mpart[rA], mpart[64 + rA]));
            mnB = fmaxf(moB, fmaxf(mpart[rB], mpart[64 + rB]));
            scA = __expf(moA - mnA);
            scB = __expf(moB - mnB);
            float lA = 0.f, lB = 0.f;
#pragma unroll
            for (int ni = 0; ni < 4; ni++) {
                int cc = wn * 32 + ni * 8 + 2 * tg;
                float e0 = __expf(cs_[ni][0] - mnA);
                float e1 = __expf(cs_[ni][1] - mnA);
                float e2 = __expf(cs_[ni][2] - mnB);
                float e3 = __expf(cs_[ni][3] - mnB);
                lA += e0 + e1; lB += e2 + e3;
                *reinterpret_cast<float2*>(Ps + rA * LDQ + cc) = make_float2(e0, e1);
                *reinterpret_cast<float2*>(Ps + rB * LDQ + cc) = make_float2(e2, e3);
            }
            lA += __shfl_xor_sync(0xffffffffu, lA, 1);
            lA += __shfl_xor_sync(0xffffffffu, lA, 2);
            lB += __shfl_xor_sync(0xffffffffu, lB, 1);
            lB += __shfl_xor_sync(0xffffffffu, lB, 2);
            if (tg == 0) { lpart[wn * 64 + rA] = lA; lpart[wn * 64 + rB] = lB; }
            // rescale O accumulators locally
#pragma unroll
            for (int ni = 0; ni < 4; ni++) {
                co[ni][0] *= scA; co[ni][1] *= scA;
                co[ni][2] *= scB; co[ni][3] *= scB;
            }
        }
        __syncthreads();

        // ---- one thread per row updates running stats ----
        if (wn == 0 && tg == 0) {
            rowl[rA] = rowl[rA] * scA + lpart[rA] + lpart[64 + rA];
            rowm[rA] = mnA;
            rowl[rB] = rowl[rB] * scB + lpart[rB] + lpart[64 + rB];
            rowm[rB] = mnB;
        }

        // ---- O += P @ V ----
        {
            const uint32_t aP = psu + ((wm * 16 + r15) * LDQ) * 4 + ch16;
            const float* Vb = Vs + buf * VTI;
#pragma unroll
            for (int ks = 0; ks < 8; ks++) {
                uint32_t pa[4];
                ldsm4(pa, aP + ks * 32);
                const float* vrow = Vb + (ks * 8 + tg) * LDV;
#pragma unroll
                for (int ni = 0; ni < 4; ni++) {
                    int n0g = wn * 32 + ni * 8 + g;
                    uint32_t b0 = __float_as_uint(vrow[n0g]);
                    uint32_t b1 = __float_as_uint(vrow[4 * LDV + n0g]);
                    mma_tf32(co[ni], pa, b0, b1);
                }
            }
        }
        __syncthreads();
    }

    // ---- final write ----
    {
        int b = bh >> 4, h = bh & 15;
        float il_g  = 1.0f / rowl[rA];
        float il_g8 = 1.0f / rowl[rB];
#pragma unroll
        for (int half = 0; half < 2; half++) {
            int r = wm * 16 + g + half * 8;
            float il = half ? il_g8 : il_g;
            size_t grow = ((size_t)b * SEQ + qbase + r) * DMODEL + h * 64;
#pragma unroll
            for (int ni = 0; ni < 4; ni++) {
                int d0 = wn * 32 + ni * 8 + tg * 2;
                float2 v = make_float2(co[ni][half*2] * il, co[ni][half*2+1] * il);
                *reinterpret_cast<float2*>(ctx + grow + d0) = v;
            }
        }
    }
}

// ----------------------------------------------------------------------------
// Launch
// ----------------------------------------------------------------------------
extern "C" void kernel_launch(void* const* d_in, const int* in_sizes, int n_in,
                              void* d_out, int out_size) {
    const float* x  = (const float*)d_in[0];
    const float* wq = (const float*)d_in[2];
    const float* wk = (const float*)d_in[3];
    const float* wv = (const float*)d_in[4];
    const float* wo = (const float*)d_in[5];
    const float* w1 = (const float*)d_in[6];
    const float* w2 = (const float*)d_in[7];
    const float* g1 = (const float*)d_in[8];
    const float* g2 = (const float*)d_in[9];
    float* out = (float*)d_out;

    static float *p_h=nullptr,*p_q=nullptr,*p_k=nullptr,*p_v=nullptr,
                 *p_ctx=nullptr,*p_x2=nullptr,*p_ffn=nullptr;
    if (!p_h) {
        cudaGetSymbolAddress((void**)&p_h,    g_h);
        cudaGetSymbolAddress((void**)&p_q,    g_q);
        cudaGetSymbolAddress((void**)&p_k,    g_k);
        cudaGetSymbolAddress((void**)&p_v,    g_v);
        cudaGetSymbolAddress((void**)&p_ctx,  g_ctx);
        cudaGetSymbolAddress((void**)&p_x2,   g_x2);
        cudaGetSymbolAddress((void**)&p_ffn,  g_ffn);
        cudaFuncSetAttribute(gemm_mma<0>, cudaFuncAttributeMaxDynamicSharedMemorySize, GEMM_SMEM);
        cudaFuncSetAttribute(gemm_mma<3>, cudaFuncAttributeMaxDynamicSharedMemorySize, GEMM_SMEM);
        cudaFuncSetAttribute(gemm_mma<4>, cudaFuncAttributeMaxDynamicSharedMemorySize, GEMM_SMEM);
        cudaFuncSetAttribute(flash_attn_tc, cudaFuncAttributeMaxDynamicSharedMemorySize, FA_SMEM);
    }

    build_rope_table<<<(SEQ * 32 + 255) / 256, 256>>>();

    // --- attention sublayer ---
    rmsnorm_k<<<ROWS, 256>>>(x, g1, p_h);

    dim3 gqkv(3 * DMODEL / 256, ROWS / 128);   // (12, 32)
    gemm_mma<4><<<gqkv, 256, GEMM_SMEM>>>(p_h, wq, wk, wv, nullptr,
                                          p_q, p_k, p_v, ROWS, 3 * DMODEL, DMODEL);

    flash_attn_tc<<<dim3(SEQ / 64, BATCH * NHEAD), 256, FA_SMEM>>>(p_q, p_k, p_v, p_ctx);

    dim3 gproj(DMODEL / 256, ROWS / 128);      // (4, 32)
    gemm_mma<0><<<gproj, 256, GEMM_SMEM>>>(p_ctx, wo, nullptr, nullptr, x,
                                           p_x2, nullptr, nullptr, ROWS, DMODEL, DMODEL);

    // --- FFN sublayer ---
    rmsnorm_k<<<ROWS, 256>>>(p_x2, g2, p_h);
    dim3 gup(2 * DFF / 256, ROWS / 128);       // (32, 32)
    gemm_mma<3><<<gup, 256, GEMM_SMEM>>>(p_h, w1, nullptr, nullptr, nullptr,
                                         p_ffn, nullptr, nullptr, ROWS, 2 * DFF, DMODEL);
    dim3 gdown(DMODEL / 256, ROWS / 128);      // (4, 32)
    gemm_mma<0><<<gdown, 256, GEMM_SMEM>>>(p_ffn, w2, nullptr, nullptr, p_x2,
                                           out, nullptr, nullptr, ROWS, DMODEL, DFF);
}